// round 2
// baseline (speedup 1.0000x reference)
#include <cuda_runtime.h>
#include <cuda_bf16.h>
#include <math.h>

// Problem constants
#define B 4
#define C 128
#define NSP 4096          // H*W*D = 16*16*16
#define G 32
#define CPG 4             // C / G
#define DH 128            // head dim == C
#define BM 64             // query tile
#define BN 64             // kv tile

// Scratch (allocation-free rule: __device__ globals)
__device__ float g_xn[B * C * NSP];        // groupnorm output, (b,c,s)
__device__ float g_q [B * NSP * C];        // (b,n,c)
__device__ float g_k [B * NSP * C];        // (b,n,c)
__device__ float g_v [B * NSP * C];        // (b,n,c)
__device__ float g_ao[B * NSP * C];        // attention output (b,n,c)

// ---------------------------------------------------------------------------
// Kernel 1: GroupNorm. One block per (b, group). 16384 elems per group.
// ---------------------------------------------------------------------------
__global__ __launch_bounds__(256) void gn_kernel(const float* __restrict__ x,
                                                 const float* __restrict__ gw,
                                                 const float* __restrict__ gb) {
    __shared__ float rs[256], rs2[256];
    int tid = threadIdx.x;
    int b = blockIdx.x >> 5;
    int g = blockIdx.x & 31;
    const float4* xp = (const float4*)(x + ((size_t)b * C + g * CPG) * NSP);
    float4* yp = (float4*)(g_xn + ((size_t)b * C + g * CPG) * NSP);

    float s = 0.f, s2 = 0.f;
    for (int i = tid; i < CPG * NSP / 4; i += 256) {
        float4 v = xp[i];
        s  += v.x + v.y + v.z + v.w;
        s2 += v.x * v.x + v.y * v.y + v.z * v.z + v.w * v.w;
    }
    rs[tid] = s; rs2[tid] = s2;
    __syncthreads();
    #pragma unroll
    for (int off = 128; off > 0; off >>= 1) {
        if (tid < off) { rs[tid] += rs[tid + off]; rs2[tid] += rs2[tid + off]; }
        __syncthreads();
    }
    const float invN = 1.0f / (CPG * NSP);
    float mean = rs[0] * invN;
    float var  = rs2[0] * invN - mean * mean;
    float rstd = rsqrtf(var + 1e-5f);

    for (int i = tid; i < CPG * NSP / 4; i += 256) {
        int c = g * CPG + (i >> 10);         // 1024 float4 per channel
        float wch = gw[c] * rstd;
        float bch = gb[c] - mean * wch;
        float4 v = xp[i];
        v.x = v.x * wch + bch;
        v.y = v.y * wch + bch;
        v.z = v.z * wch + bch;
        v.w = v.w * wch + bch;
        yp[i] = v;
    }
}

// ---------------------------------------------------------------------------
// Kernel 2: QKV projection GEMM. out[o,s] = sum_c W[o,c]*xn[b,c,s] + bias[o]
// scattered into q/k/v with (b,n,c) layout. Tile 64x64, 256 thr, 4x4 micro.
// Dynamic smem: As[128][68] + Bs[128][68]
// ---------------------------------------------------------------------------
#define QLD 68
__global__ __launch_bounds__(256) void qkv_kernel(const float* __restrict__ w,
                                                  const float* __restrict__ bias) {
    extern __shared__ float qsm[];
    float* As = qsm;                 // [128][QLD]  W transposed: As[c][o_local]
    float* Bs = qsm + 128 * QLD;     // [128][QLD]  xn tile:      Bs[c][s_local]
    int tid = threadIdx.x;
    int o0 = blockIdx.x * 64;
    int s0 = blockIdx.y * 64;
    int b  = blockIdx.z;

    // load W tile transposed (64 rows of 128 floats)
    for (int i = tid; i < 64 * 32; i += 256) {
        int r = i >> 5, c4 = i & 31;
        float4 v = ((const float4*)(w + (size_t)(o0 + r) * 128))[c4];
        int c = c4 * 4;
        As[(c + 0) * QLD + r] = v.x; As[(c + 1) * QLD + r] = v.y;
        As[(c + 2) * QLD + r] = v.z; As[(c + 3) * QLD + r] = v.w;
    }
    // load xn tile (rows = channels, contiguous over s)
    for (int i = tid; i < 128 * 16; i += 256) {
        int c = i >> 4, s4 = i & 15;
        ((float4*)&Bs[c * QLD])[s4] =
            ((const float4*)(g_xn + ((size_t)b * C + c) * NSP + s0))[s4];
    }
    __syncthreads();

    int ty = tid >> 4, tx = tid & 15;
    float acc[4][4] = {};
    #pragma unroll 4
    for (int k = 0; k < 128; k++) {
        float4 a  = *(const float4*)&As[k * QLD + ty * 4];
        float4 bb = *(const float4*)&Bs[k * QLD + tx * 4];
        acc[0][0] += a.x * bb.x; acc[0][1] += a.x * bb.y; acc[0][2] += a.x * bb.z; acc[0][3] += a.x * bb.w;
        acc[1][0] += a.y * bb.x; acc[1][1] += a.y * bb.y; acc[1][2] += a.y * bb.z; acc[1][3] += a.y * bb.w;
        acc[2][0] += a.z * bb.x; acc[2][1] += a.z * bb.y; acc[2][2] += a.z * bb.z; acc[2][3] += a.z * bb.w;
        acc[3][0] += a.w * bb.x; acc[3][1] += a.w * bb.y; acc[3][2] += a.w * bb.z; acc[3][3] += a.w * bb.w;
    }

    #pragma unroll
    for (int i = 0; i < 4; i++) {
        int o = o0 + ty * 4 + i;
        float bv = bias[o];
        float* dst; int oc;
        if (o < 128)      { dst = g_q; oc = o; }
        else if (o < 256) { dst = g_k; oc = o - 128; }
        else              { dst = g_v; oc = o - 256; }
        #pragma unroll
        for (int j = 0; j < 4; j++) {
            int s = s0 + tx * 4 + j;
            dst[((size_t)b * NSP + s) * C + oc] = acc[i][j] + bv;
        }
    }
}

// ---------------------------------------------------------------------------
// Kernel 3: flash attention, fp32. Block = 64 query rows, loops over 64-wide
// KV tiles with online softmax. 256 threads. Dynamic smem.
// ---------------------------------------------------------------------------
#define SS_LD 68
__global__ __launch_bounds__(256) void attn_kernel() {
    extern __shared__ float sm[];
    float* Qt   = sm;                  // [DH][BM]  (k-major)
    float* Kt   = Qt + DH * BM;        // [DH][BN]  (k-major)
    float* Vs   = Kt + DH * BN;        // [BN][DH]  (row-major)
    float* Ss   = Vs + BN * DH;        // [BM][SS_LD]
    float* marr = Ss + BM * SS_LD;     // [BM]
    float* aarr = marr + BM;           // [BM]
    float* larr = aarr + BM;           // [BM]
    float* redm = larr + BM;           // [BM][4]
    float* reds = redm + BM * 4;       // [BM][4]

    int tid = threadIdx.x;
    int b = blockIdx.y;
    int q0 = blockIdx.x * BM;
    const float scale = 0.08838834764831845f;   // 128^-0.5

    // load Q tile transposed + pre-scaled
    const float4* qg = (const float4*)(g_q + ((size_t)b * NSP + q0) * DH);
    for (int i = tid; i < BM * DH / 4; i += 256) {
        int r = i >> 5, c4 = i & 31;
        float4 v = qg[i];
        int c = c4 * 4;
        Qt[(c + 0) * BM + r] = v.x * scale;
        Qt[(c + 1) * BM + r] = v.y * scale;
        Qt[(c + 2) * BM + r] = v.z * scale;
        Qt[(c + 3) * BM + r] = v.w * scale;
    }
    if (tid < BM) { marr[tid] = -1e30f; larr[tid] = 0.f; }

    float O[4][8];
    #pragma unroll
    for (int i = 0; i < 4; i++)
        #pragma unroll
        for (int j = 0; j < 8; j++) O[i][j] = 0.f;

    int ty = tid >> 4, tx = tid & 15;      // ty: row group (4 rows), tx: cols
    int rB = tid >> 2, jB = tid & 3;       // phase-B mapping

    for (int kt = 0; kt < NSP / BN; kt++) {
        __syncthreads();   // previous tile fully consumed; Qt ready on iter 0
        const float4* kg = (const float4*)(g_k + ((size_t)b * NSP + kt * BN) * DH);
        const float4* vg = (const float4*)(g_v + ((size_t)b * NSP + kt * BN) * DH);
        for (int i = tid; i < BN * DH / 4; i += 256) {
            int r = i >> 5, c4 = i & 31;
            float4 kv = kg[i];
            int c = c4 * 4;
            Kt[(c + 0) * BN + r] = kv.x;
            Kt[(c + 1) * BN + r] = kv.y;
            Kt[(c + 2) * BN + r] = kv.z;
            Kt[(c + 3) * BN + r] = kv.w;
            ((float4*)Vs)[i] = vg[i];
        }
        __syncthreads();

        // Phase A: S = Q K^T (64x64, K=128)
        float acc[4][4] = {};
        #pragma unroll 4
        for (int k = 0; k < DH; k++) {
            float4 qa = *(const float4*)&Qt[k * BM + ty * 4];
            float4 kb = *(const float4*)&Kt[k * BN + tx * 4];
            acc[0][0] += qa.x * kb.x; acc[0][1] += qa.x * kb.y; acc[0][2] += qa.x * kb.z; acc[0][3] += qa.x * kb.w;
            acc[1][0] += qa.y * kb.x; acc[1][1] += qa.y * kb.y; acc[1][2] += qa.y * kb.z; acc[1][3] += qa.y * kb.w;
            acc[2][0] += qa.z * kb.x; acc[2][1] += qa.z * kb.y; acc[2][2] += qa.z * kb.z; acc[2][3] += qa.z * kb.w;
            acc[3][0] += qa.w * kb.x; acc[3][1] += qa.w * kb.y; acc[3][2] += qa.w * kb.z; acc[3][3] += qa.w * kb.w;
        }
        #pragma unroll
        for (int i = 0; i < 4; i++)
            *(float4*)&Ss[(ty * 4 + i) * SS_LD + tx * 4] =
                make_float4(acc[i][0], acc[i][1], acc[i][2], acc[i][3]);
        __syncthreads();

        // Phase B: online softmax stats (4 threads per row, 16 cols each)
        float lm = -1e30f;
        #pragma unroll
        for (int c = 0; c < 16; c++) lm = fmaxf(lm, Ss[rB * SS_LD + jB * 16 + c]);
        redm[rB * 4 + jB] = lm;
        __syncthreads();
        if (jB == 0) {
            float m4 = fmaxf(fmaxf(redm[rB * 4], redm[rB * 4 + 1]),
                             fmaxf(redm[rB * 4 + 2], redm[rB * 4 + 3]));
            float mold = marr[rB];
            float mnew = fmaxf(mold, m4);
            aarr[rB] = __expf(mold - mnew);
            marr[rB] = mnew;
        }
        __syncthreads();
        float mnew = marr[rB];
        float ls = 0.f;
        #pragma unroll
        for (int c = 0; c < 16; c++) {
            float p = __expf(Ss[rB * SS_LD + jB * 16 + c] - mnew);
            Ss[rB * SS_LD + jB * 16 + c] = p;
            ls += p;
        }
        reds[rB * 4 + jB] = ls;
        __syncthreads();
        if (jB == 0)
            larr[rB] = larr[rB] * aarr[rB] +
                       (reds[rB * 4] + reds[rB * 4 + 1] + reds[rB * 4 + 2] + reds[rB * 4 + 3]);

        // Phase C: O = O*alpha + P V   (rows ty*4.., cols tx*8..)
        #pragma unroll
        for (int i = 0; i < 4; i++) {
            float al = aarr[ty * 4 + i];
            #pragma unroll
            for (int j = 0; j < 8; j++) O[i][j] *= al;
        }
        #pragma unroll 2
        for (int m = 0; m < BN; m++) {
            float p0 = Ss[(ty * 4 + 0) * SS_LD + m];
            float p1 = Ss[(ty * 4 + 1) * SS_LD + m];
            float p2 = Ss[(ty * 4 + 2) * SS_LD + m];
            float p3 = Ss[(ty * 4 + 3) * SS_LD + m];
            float4 v0 = *(const float4*)&Vs[m * DH + tx * 8];
            float4 v1 = *(const float4*)&Vs[m * DH + tx * 8 + 4];
            O[0][0] += p0 * v0.x; O[0][1] += p0 * v0.y; O[0][2] += p0 * v0.z; O[0][3] += p0 * v0.w;
            O[0][4] += p0 * v1.x; O[0][5] += p0 * v1.y; O[0][6] += p0 * v1.z; O[0][7] += p0 * v1.w;
            O[1][0] += p1 * v0.x; O[1][1] += p1 * v0.y; O[1][2] += p1 * v0.z; O[1][3] += p1 * v0.w;
            O[1][4] += p1 * v1.x; O[1][5] += p1 * v1.y; O[1][6] += p1 * v1.z; O[1][7] += p1 * v1.w;
            O[2][0] += p2 * v0.x; O[2][1] += p2 * v0.y; O[2][2] += p2 * v0.z; O[2][3] += p2 * v0.w;
            O[2][4] += p2 * v1.x; O[2][5] += p2 * v1.y; O[2][6] += p2 * v1.z; O[2][7] += p2 * v1.w;
            O[3][0] += p3 * v0.x; O[3][1] += p3 * v0.y; O[3][2] += p3 * v0.z; O[3][3] += p3 * v0.w;
            O[3][4] += p3 * v1.x; O[3][5] += p3 * v1.y; O[3][6] += p3 * v1.z; O[3][7] += p3 * v1.w;
        }
    }
    __syncthreads();   // larr final

    #pragma unroll
    for (int i = 0; i < 4; i++) {
        float rinv = 1.0f / larr[ty * 4 + i];
        float* dst = g_ao + ((size_t)b * NSP + q0 + ty * 4 + i) * DH + tx * 8;
        *(float4*)dst       = make_float4(O[i][0] * rinv, O[i][1] * rinv, O[i][2] * rinv, O[i][3] * rinv);
        *(float4*)(dst + 4) = make_float4(O[i][4] * rinv, O[i][5] * rinv, O[i][6] * rinv, O[i][7] * rinv);
    }
}

// ---------------------------------------------------------------------------
// Kernel 4: out projection + bias + residual. out[b,o,s] layout. Dynamic smem.
// ---------------------------------------------------------------------------
__global__ __launch_bounds__(256) void oproj_kernel(const float* __restrict__ w,
                                                    const float* __restrict__ bias,
                                                    const float* __restrict__ x,
                                                    float* __restrict__ out) {
    extern __shared__ float osm[];
    float* As = osm;                 // [128][QLD]  W transposed
    float* Bs = osm + 128 * QLD;     // [128][QLD]  ao transposed
    int tid = threadIdx.x;
    int o0 = blockIdx.x * 64;
    int s0 = blockIdx.y * 64;
    int b  = blockIdx.z;

    for (int i = tid; i < 64 * 32; i += 256) {
        int r = i >> 5, c4 = i & 31;
        float4 v = ((const float4*)(w + (size_t)(o0 + r) * 128))[c4];
        int c = c4 * 4;
        As[(c + 0) * QLD + r] = v.x; As[(c + 1) * QLD + r] = v.y;
        As[(c + 2) * QLD + r] = v.z; As[(c + 3) * QLD + r] = v.w;
    }
    for (int i = tid; i < 64 * 32; i += 256) {
        int r = i >> 5, c4 = i & 31;   // r = local s
        float4 v = ((const float4*)(g_ao + ((size_t)b * NSP + s0 + r) * C))[c4];
        int c = c4 * 4;
        Bs[(c + 0) * QLD + r] = v.x; Bs[(c + 1) * QLD + r] = v.y;
        Bs[(c + 2) * QLD + r] = v.z; Bs[(c + 3) * QLD + r] = v.w;
    }
    __syncthreads();

    int ty = tid >> 4, tx = tid & 15;
    float acc[4][4] = {};
    #pragma unroll 4
    for (int k = 0; k < 128; k++) {
        float4 a  = *(const float4*)&As[k * QLD + ty * 4];
        float4 bb = *(const float4*)&Bs[k * QLD + tx * 4];
        acc[0][0] += a.x * bb.x; acc[0][1] += a.x * bb.y; acc[0][2] += a.x * bb.z; acc[0][3] += a.x * bb.w;
        acc[1][0] += a.y * bb.x; acc[1][1] += a.y * bb.y; acc[1][2] += a.y * bb.z; acc[1][3] += a.y * bb.w;
        acc[2][0] += a.z * bb.x; acc[2][1] += a.z * bb.y; acc[2][2] += a.z * bb.z; acc[2][3] += a.z * bb.w;
        acc[3][0] += a.w * bb.x; acc[3][1] += a.w * bb.y; acc[3][2] += a.w * bb.z; acc[3][3] += a.w * bb.w;
    }

    #pragma unroll
    for (int i = 0; i < 4; i++) {
        int o = o0 + ty * 4 + i;
        float bv = bias[o];
        size_t base = ((size_t)b * C + o) * NSP + s0 + tx * 4;
        float4 xv = *(const float4*)(x + base);
        float4 r = make_float4(acc[i][0] + bv + xv.x, acc[i][1] + bv + xv.y,
                               acc[i][2] + bv + xv.z, acc[i][3] + bv + xv.w);
        *(float4*)(out + base) = r;
    }
}

// ---------------------------------------------------------------------------
extern "C" void kernel_launch(void* const* d_in, const int* in_sizes, int n_in,
                              void* d_out, int out_size) {
    const float* x     = (const float*)d_in[0];
    const float* gn_w  = (const float*)d_in[1];
    const float* gn_b  = (const float*)d_in[2];
    const float* qkv_w = (const float*)d_in[3];
    const float* qkv_b = (const float*)d_in[4];
    const float* out_w = (const float*)d_in[5];
    const float* out_b = (const float*)d_in[6];
    float* out = (float*)d_out;

    static bool attrs_set = false;
    const int gemm_smem = 2 * 128 * QLD * sizeof(float);
    const int attn_smem = (DH * BM + DH * BN + BN * DH + BM * SS_LD + BM * 3 + BM * 8) * sizeof(float);
    if (!attrs_set) {
        cudaFuncSetAttribute(qkv_kernel,  cudaFuncAttributeMaxDynamicSharedMemorySize, gemm_smem);
        cudaFuncSetAttribute(oproj_kernel, cudaFuncAttributeMaxDynamicSharedMemorySize, gemm_smem);
        cudaFuncSetAttribute(attn_kernel, cudaFuncAttributeMaxDynamicSharedMemorySize, attn_smem);
        attrs_set = true;
    }

    gn_kernel<<<B * G, 256>>>(x, gn_w, gn_b);
    qkv_kernel<<<dim3(6, NSP / 64, B), 256, gemm_smem>>>(qkv_w, qkv_b);
    attn_kernel<<<dim3(NSP / BM, B), 256, attn_smem>>>();
    oproj_kernel<<<dim3(2, NSP / 64, B), 256, gemm_smem>>>(out_w, out_b, x, out);
}

// round 5
// speedup vs baseline: 6.9523x; 6.9523x over previous
#include <cuda_runtime.h>
#include <cuda_bf16.h>
#include <math.h>
#include <cstdint>

// Problem constants
#define B 4
#define C 128
#define NSP 4096          // H*W*D
#define G 32
#define CPG 4             // C / G
#define DH 128

// Scratch (allocation-free rule: __device__ globals)
__device__ float g_xn[B * C * NSP];              // groupnorm output, (b,c,s)
__device__ __nv_bfloat16 g_qh[B * NSP * C];      // (b,n,c), pre-scaled by c^-0.5*log2(e)
__device__ __nv_bfloat16 g_kh[B * NSP * C];      // (b,n,c)
__device__ __nv_bfloat16 g_vt[B * C * NSP];      // (b,c,n)  transposed V
__device__ float g_ao[B * NSP * C];              // attention output (b,n,c)

// ---------------------------------------------------------------------------
// helpers
// ---------------------------------------------------------------------------
__device__ __forceinline__ uint32_t smem_u32(const void* p) {
    uint32_t a;
    asm("{ .reg .u64 t; cvta.to.shared.u64 t, %1; cvt.u32.u64 %0, t; }"
        : "=r"(a) : "l"(p));
    return a;
}
__device__ __forceinline__ void ldsm4(uint32_t& r0, uint32_t& r1, uint32_t& r2,
                                      uint32_t& r3, uint32_t addr) {
    asm volatile("ldmatrix.sync.aligned.m8n8.x4.shared.b16 {%0,%1,%2,%3}, [%4];"
        : "=r"(r0), "=r"(r1), "=r"(r2), "=r"(r3) : "r"(addr));
}
__device__ __forceinline__ void mma16816(float* c, const uint32_t* a,
                                         uint32_t b0, uint32_t b1) {
    asm volatile(
        "mma.sync.aligned.m16n8k16.row.col.f32.bf16.bf16.f32 "
        "{%0,%1,%2,%3}, {%4,%5,%6,%7}, {%8,%9}, {%0,%1,%2,%3};"
        : "+f"(c[0]), "+f"(c[1]), "+f"(c[2]), "+f"(c[3])
        : "r"(a[0]), "r"(a[1]), "r"(a[2]), "r"(a[3]), "r"(b0), "r"(b1));
}
__device__ __forceinline__ uint32_t packbf(float lo, float hi) {
    uint32_t r;
    asm("cvt.rn.bf16x2.f32 %0, %1, %2;" : "=r"(r) : "f"(hi), "f"(lo));
    return r;
}

// ---------------------------------------------------------------------------
// Kernel 1: GroupNorm
// ---------------------------------------------------------------------------
__global__ __launch_bounds__(256) void gn_kernel(const float* __restrict__ x,
                                                 const float* __restrict__ gw,
                                                 const float* __restrict__ gb) {
    __shared__ float rs[256], rs2[256];
    int tid = threadIdx.x;
    int b = blockIdx.x >> 5;
    int g = blockIdx.x & 31;
    const float4* xp = (const float4*)(x + ((size_t)b * C + g * CPG) * NSP);
    float4* yp = (float4*)(g_xn + ((size_t)b * C + g * CPG) * NSP);

    float s = 0.f, s2 = 0.f;
    for (int i = tid; i < CPG * NSP / 4; i += 256) {
        float4 v = xp[i];
        s  += v.x + v.y + v.z + v.w;
        s2 += v.x * v.x + v.y * v.y + v.z * v.z + v.w * v.w;
    }
    rs[tid] = s; rs2[tid] = s2;
    __syncthreads();
    #pragma unroll
    for (int off = 128; off > 0; off >>= 1) {
        if (tid < off) { rs[tid] += rs[tid + off]; rs2[tid] += rs2[tid + off]; }
        __syncthreads();
    }
    const float invN = 1.0f / (CPG * NSP);
    float mean = rs[0] * invN;
    float var  = rs2[0] * invN - mean * mean;
    float rstd = rsqrtf(var + 1e-5f);

    for (int i = tid; i < CPG * NSP / 4; i += 256) {
        int c = g * CPG + (i >> 10);
        float wch = gw[c] * rstd;
        float bch = gb[c] - mean * wch;
        float4 v = xp[i];
        v.x = v.x * wch + bch;
        v.y = v.y * wch + bch;
        v.z = v.z * wch + bch;
        v.w = v.w * wch + bch;
        yp[i] = v;
    }
}

// ---------------------------------------------------------------------------
// Kernel 2: QKV projection GEMM -> bf16 q/k (b,s,c) + transposed bf16 v (b,c,s)
// ---------------------------------------------------------------------------
#define QLD 68
__global__ __launch_bounds__(256) void qkv_kernel(const float* __restrict__ w,
                                                  const float* __restrict__ bias) {
    extern __shared__ float qsm[];
    float* As = qsm;                 // [128][QLD]  W^T
    float* Bs = qsm + 128 * QLD;     // [128][QLD]  xn tile
    int tid = threadIdx.x;
    int o0 = blockIdx.x * 64;
    int s0 = blockIdx.y * 64;
    int b  = blockIdx.z;

    for (int i = tid; i < 64 * 32; i += 256) {
        int r = i >> 5, c4 = i & 31;
        float4 v = ((const float4*)(w + (size_t)(o0 + r) * 128))[c4];
        int c = c4 * 4;
        As[(c + 0) * QLD + r] = v.x; As[(c + 1) * QLD + r] = v.y;
        As[(c + 2) * QLD + r] = v.z; As[(c + 3) * QLD + r] = v.w;
    }
    for (int i = tid; i < 128 * 16; i += 256) {
        int c = i >> 4, s4 = i & 15;
        ((float4*)&Bs[c * QLD])[s4] =
            ((const float4*)(g_xn + ((size_t)b * C + c) * NSP + s0))[s4];
    }
    __syncthreads();

    int ty = tid >> 4, tx = tid & 15;
    float acc[4][4] = {};
    #pragma unroll 4
    for (int k = 0; k < 128; k++) {
        float4 a  = *(const float4*)&As[k * QLD + ty * 4];
        float4 bb = *(const float4*)&Bs[k * QLD + tx * 4];
        acc[0][0] += a.x * bb.x; acc[0][1] += a.x * bb.y; acc[0][2] += a.x * bb.z; acc[0][3] += a.x * bb.w;
        acc[1][0] += a.y * bb.x; acc[1][1] += a.y * bb.y; acc[1][2] += a.y * bb.z; acc[1][3] += a.y * bb.w;
        acc[2][0] += a.z * bb.x; acc[2][1] += a.z * bb.y; acc[2][2] += a.z * bb.z; acc[2][3] += a.z * bb.w;
        acc[3][0] += a.w * bb.x; acc[3][1] += a.w * bb.y; acc[3][2] += a.w * bb.z; acc[3][3] += a.w * bb.w;
    }

    // scale = 128^-0.5 * log2(e): folds softmax's exp->exp2 conversion into Q
    const float scale = 0.1275174331f;
    #pragma unroll
    for (int i = 0; i < 4; i++) {
        int o = o0 + ty * 4 + i;
        float bv = bias[o];
        #pragma unroll
        for (int j = 0; j < 4; j++) {
            int s = s0 + tx * 4 + j;
            float val = acc[i][j] + bv;
            if (o < 128) {
                g_qh[((size_t)b * NSP + s) * C + o] = __float2bfloat16(val * scale);
            } else if (o < 256) {
                g_kh[((size_t)b * NSP + s) * C + (o - 128)] = __float2bfloat16(val);
            } else {
                g_vt[((size_t)b * C + (o - 256)) * NSP + s] = __float2bfloat16(val);
            }
        }
    }
}

// ---------------------------------------------------------------------------
// Kernel 3: flash attention with mma.sync (HMMA) bf16.
// 8 warps, warp w owns q rows [w*16, w*16+16). 128-wide KV tiles.
// ---------------------------------------------------------------------------
#define LDB 272                      // smem bytes per 128-bf16 row (136 halves)
#define SM_ATTN (3 * 128 * LDB)      // Q, K, V tiles

__global__ __launch_bounds__(256, 1) void attn_kernel() {
    extern __shared__ char smraw[];
    uint32_t smem = smem_u32(smraw);
    const uint32_t Qs = smem;
    const uint32_t Ks = smem + 128 * LDB;
    const uint32_t Vs = smem + 2 * 128 * LDB;

    int tid = threadIdx.x;
    int w = tid >> 5, t = tid & 31;
    int b = blockIdx.y, q0 = blockIdx.x * 128;

    // stage Q tile (rows = q, 128 bf16 each)
    {
        const uint4* src = (const uint4*)(g_qh + ((size_t)(b * NSP + q0) << 7));
        for (int i = tid; i < 2048; i += 256) {
            int r = i >> 4, c = i & 15;
            *(uint4*)(smraw + r * LDB + c * 16) = src[i];
        }
    }
    __syncthreads();

    // Q fragments (row-major A, m16k16 per k-step)
    uint32_t qf[8][4];
    {
        uint32_t qbase = Qs + (uint32_t)((w * 16 + (t & 7) + ((t >> 3) & 1) * 8) * LDB
                                         + (t >> 4) * 16);
        #pragma unroll
        for (int j = 0; j < 8; j++)
            ldsm4(qf[j][0], qf[j][1], qf[j][2], qf[j][3], qbase + j * 32);
    }

    // per-thread B-operand ldmatrix base (shared by K and V tiles)
    // lanes 0-15 -> rows 0-7 (k cols 0-7 / 8-15), lanes 16-31 -> rows 8-15
    uint32_t kvoff = (uint32_t)(((t & 7) + ((t >> 4) << 3)) * LDB + ((t >> 3) & 1) * 16);
    uint32_t kb = Ks + kvoff, vb = Vs + kvoff;

    float O[16][4];
    #pragma unroll
    for (int n = 0; n < 16; n++) { O[n][0] = O[n][1] = O[n][2] = O[n][3] = 0.f; }
    float m0 = -1e30f, m1 = -1e30f, l0r = 0.f, l1r = 0.f;

    for (int kt = 0; kt < NSP / 128; kt++) {
        __syncthreads();   // previous tile fully consumed
        const uint4* ksrc = (const uint4*)(g_kh + ((size_t)(b * NSP + kt * 128) << 7));
        for (int i = tid; i < 2048; i += 256) {
            int r = i >> 4, c = i & 15;
            *(uint4*)(smraw + 128 * LDB + r * LDB + c * 16) = ksrc[i];
        }
        for (int i = tid; i < 2048; i += 256) {
            int r = i >> 4, c = i & 15;
            const uint4* vsrc = (const uint4*)(g_vt + ((size_t)(b * C + r) << 12) + (kt << 7));
            *(uint4*)(smraw + 2 * 128 * LDB + r * LDB + c * 16) = vsrc[c];
        }
        __syncthreads();

        // S = Q K^T  (16 rows x 128 cols per warp; S in log2 domain via q scale)
        float S[16][4];
        #pragma unroll
        for (int n = 0; n < 16; n++) { S[n][0] = S[n][1] = S[n][2] = S[n][3] = 0.f; }
        #pragma unroll
        for (int n2 = 0; n2 < 8; n2++) {
            uint32_t kaddr = kb + n2 * (16 * LDB);     // FIX: x4 ldmatrix spans 16 rows
            #pragma unroll
            for (int j = 0; j < 8; j++) {
                uint32_t f0, f1, f2, f3;
                ldsm4(f0, f1, f2, f3, kaddr + j * 32);
                mma16816(S[2 * n2],     qf[j], f0, f1);
                mma16816(S[2 * n2 + 1], qf[j], f2, f3);
            }
        }

        // online softmax (rows r0=t/4, r1=t/4+8)
        float mx0 = -1e30f, mx1 = -1e30f;
        #pragma unroll
        for (int n = 0; n < 16; n++) {
            mx0 = fmaxf(mx0, fmaxf(S[n][0], S[n][1]));
            mx1 = fmaxf(mx1, fmaxf(S[n][2], S[n][3]));
        }
        mx0 = fmaxf(mx0, __shfl_xor_sync(0xffffffffu, mx0, 1));
        mx0 = fmaxf(mx0, __shfl_xor_sync(0xffffffffu, mx0, 2));
        mx1 = fmaxf(mx1, __shfl_xor_sync(0xffffffffu, mx1, 1));
        mx1 = fmaxf(mx1, __shfl_xor_sync(0xffffffffu, mx1, 2));
        float mn0 = fmaxf(m0, mx0), mn1 = fmaxf(m1, mx1);
        float a0 = exp2f(m0 - mn0), a1 = exp2f(m1 - mn1);
        m0 = mn0; m1 = mn1;

        float s0 = 0.f, s1 = 0.f;
        #pragma unroll
        for (int n = 0; n < 16; n++) {
            S[n][0] = exp2f(S[n][0] - mn0);
            S[n][1] = exp2f(S[n][1] - mn0);
            S[n][2] = exp2f(S[n][2] - mn1);
            S[n][3] = exp2f(S[n][3] - mn1);
            s0 += S[n][0] + S[n][1];
            s1 += S[n][2] + S[n][3];
        }
        s0 += __shfl_xor_sync(0xffffffffu, s0, 1);
        s0 += __shfl_xor_sync(0xffffffffu, s0, 2);
        s1 += __shfl_xor_sync(0xffffffffu, s1, 1);
        s1 += __shfl_xor_sync(0xffffffffu, s1, 2);
        l0r = l0r * a0 + s0;
        l1r = l1r * a1 + s1;

        #pragma unroll
        for (int n = 0; n < 16; n++) {
            O[n][0] *= a0; O[n][1] *= a0; O[n][2] *= a1; O[n][3] *= a1;
        }

        // O += P V   (P fragments rebuilt from S regs — FA2 layout reuse)
        #pragma unroll
        for (int j = 0; j < 8; j++) {
            uint32_t pa[4];
            pa[0] = packbf(S[2 * j][0],     S[2 * j][1]);
            pa[1] = packbf(S[2 * j][2],     S[2 * j][3]);
            pa[2] = packbf(S[2 * j + 1][0], S[2 * j + 1][1]);
            pa[3] = packbf(S[2 * j + 1][2], S[2 * j + 1][3]);
            uint32_t vaddr = vb + j * 32;
            #pragma unroll
            for (int d2 = 0; d2 < 8; d2++) {
                uint32_t f0, f1, f2, f3;
                ldsm4(f0, f1, f2, f3, vaddr + d2 * (16 * LDB));   // FIX: 16-row span
                mma16816(O[2 * d2],     pa, f0, f1);
                mma16816(O[2 * d2 + 1], pa, f2, f3);
            }
        }
    }

    // epilogue: normalize, store fp32 (b, q0+row, d)
    float r0 = 1.0f / l0r, r1 = 1.0f / l1r;
    int g = t >> 2, tg = t & 3;
    float* dst0 = g_ao + ((size_t)(b * NSP + q0 + w * 16 + g) << 7) + tg * 2;
    float* dst1 = dst0 + (8 << 7);
    #pragma unroll
    for (int n = 0; n < 16; n++) {
        *(float2*)(dst0 + n * 8) = make_float2(O[n][0] * r0, O[n][1] * r0);
        *(float2*)(dst1 + n * 8) = make_float2(O[n][2] * r1, O[n][3] * r1);
    }
}

// ---------------------------------------------------------------------------
// Kernel 4: out projection + bias + residual
// ---------------------------------------------------------------------------
__global__ __launch_bounds__(256) void oproj_kernel(const float* __restrict__ w,
                                                    const float* __restrict__ bias,
                                                    const float* __restrict__ x,
                                                    float* __restrict__ out) {
    extern __shared__ float osm[];
    float* As = osm;
    float* Bs = osm + 128 * QLD;
    int tid = threadIdx.x;
    int o0 = blockIdx.x * 64;
    int s0 = blockIdx.y * 64;
    int b  = blockIdx.z;

    for (int i = tid; i < 64 * 32; i += 256) {
        int r = i >> 5, c4 = i & 31;
        float4 v = ((const float4*)(w + (size_t)(o0 + r) * 128))[c4];
        int c = c4 * 4;
        As[(c + 0) * QLD + r] = v.x; As[(c + 1) * QLD + r] = v.y;
        As[(c + 2) * QLD + r] = v.z; As[(c + 3) * QLD + r] = v.w;
    }
    for (int i = tid; i < 64 * 32; i += 256) {
        int r = i >> 5, c4 = i & 31;
        float4 v = ((const float4*)(g_ao + ((size_t)b * NSP + s0 + r) * C))[c4];
        int c = c4 * 4;
        Bs[(c + 0) * QLD + r] = v.x; Bs[(c + 1) * QLD + r] = v.y;
        Bs[(c + 2) * QLD + r] = v.z; Bs[(c + 3) * QLD + r] = v.w;
    }
    __syncthreads();

    int ty = tid >> 4, tx = tid & 15;
    float acc[4][4] = {};
    #pragma unroll 4
    for (int k = 0; k < 128; k++) {
        float4 a  = *(const float4*)&As[k * QLD + ty * 4];
        float4 bb = *(const float4*)&Bs[k * QLD + tx * 4];
        acc[0][0] += a.x * bb.x; acc[0][1] += a.x * bb.y; acc[0][2] += a.x * bb.z; acc[0][3] += a.x * bb.w;
        acc[1][0] += a.y * bb.x; acc[1][1] += a.y * bb.y; acc[1][2] += a.y * bb.z; acc[1][3] += a.y * bb.w;
        acc[2][0] += a.z * bb.x; acc[2][1] += a.z * bb.y; acc[2][2] += a.z * bb.z; acc[2][3] += a.z * bb.w;
        acc[3][0] += a.w * bb.x; acc[3][1] += a.w * bb.y; acc[3][2] += a.w * bb.z; acc[3][3] += a.w * bb.w;
    }

    #pragma unroll
    for (int i = 0; i < 4; i++) {
        int o = o0 + ty * 4 + i;
        float bv = bias[o];
        size_t base = ((size_t)b * C + o) * NSP + s0 + tx * 4;
        float4 xv = *(const float4*)(x + base);
        float4 r = make_float4(acc[i][0] + bv + xv.x, acc[i][1] + bv + xv.y,
                               acc[i][2] + bv + xv.z, acc[i][3] + bv + xv.w);
        *(float4*)(out + base) = r;
    }
}

// ---------------------------------------------------------------------------
extern "C" void kernel_launch(void* const* d_in, const int* in_sizes, int n_in,
                              void* d_out, int out_size) {
    const float* x     = (const float*)d_in[0];
    const float* gn_w  = (const float*)d_in[1];
    const float* gn_b  = (const float*)d_in[2];
    const float* qkv_w = (const float*)d_in[3];
    const float* qkv_b = (const float*)d_in[4];
    const float* out_w = (const float*)d_in[5];
    const float* out_b = (const float*)d_in[6];
    float* out = (float*)d_out;

    static bool attrs_set = false;
    const int gemm_smem = 2 * 128 * QLD * sizeof(float);
    if (!attrs_set) {
        cudaFuncSetAttribute(qkv_kernel,   cudaFuncAttributeMaxDynamicSharedMemorySize, gemm_smem);
        cudaFuncSetAttribute(oproj_kernel, cudaFuncAttributeMaxDynamicSharedMemorySize, gemm_smem);
        cudaFuncSetAttribute(attn_kernel,  cudaFuncAttributeMaxDynamicSharedMemorySize, SM_ATTN);
        attrs_set = true;
    }

    gn_kernel<<<B * G, 256>>>(x, gn_w, gn_b);
    qkv_kernel<<<dim3(6, NSP / 64, B), 256, gemm_smem>>>(qkv_w, qkv_b);
    attn_kernel<<<dim3(NSP / 128, B), 256, SM_ATTN>>>();
    oproj_kernel<<<dim3(2, NSP / 64, B), 256, gemm_smem>>>(out_w, out_b, x, out);
}

// round 6
// speedup vs baseline: 9.9768x; 1.4351x over previous
#include <cuda_runtime.h>
#include <cuda_bf16.h>
#include <math.h>
#include <cstdint>

// Problem constants
#define B 4
#define C 128
#define NSP 4096          // H*W*D
#define G 32
#define CPG 4             // C / G
#define DH 128

// Scratch (allocation-free rule: __device__ globals)
__device__ float2 g_stat[B * G];                 // per (b,g): mean, rstd
__device__ __nv_bfloat16 g_qh[B * NSP * C];      // (b,n,c), pre-scaled by c^-0.5*log2(e)
__device__ __nv_bfloat16 g_kh[B * NSP * C];      // (b,n,c)
__device__ __nv_bfloat16 g_vt[B * C * NSP];      // (b,c,n)  transposed V
__device__ __nv_bfloat16 g_aoh[B * NSP * C];     // attention output (b,n,c) bf16

// ---------------------------------------------------------------------------
// helpers
// ---------------------------------------------------------------------------
__device__ __forceinline__ uint32_t smem_u32(const void* p) {
    uint32_t a;
    asm("{ .reg .u64 t; cvta.to.shared.u64 t, %1; cvt.u32.u64 %0, t; }"
        : "=r"(a) : "l"(p));
    return a;
}
__device__ __forceinline__ void ldsm4(uint32_t& r0, uint32_t& r1, uint32_t& r2,
                                      uint32_t& r3, uint32_t addr) {
    asm volatile("ldmatrix.sync.aligned.m8n8.x4.shared.b16 {%0,%1,%2,%3}, [%4];"
        : "=r"(r0), "=r"(r1), "=r"(r2), "=r"(r3) : "r"(addr));
}
__device__ __forceinline__ void ldsm4t(uint32_t& r0, uint32_t& r1, uint32_t& r2,
                                       uint32_t& r3, uint32_t addr) {
    asm volatile("ldmatrix.sync.aligned.m8n8.x4.trans.shared.b16 {%0,%1,%2,%3}, [%4];"
        : "=r"(r0), "=r"(r1), "=r"(r2), "=r"(r3) : "r"(addr));
}
__device__ __forceinline__ void mma16816(float* c, const uint32_t* a,
                                         uint32_t b0, uint32_t b1) {
    asm volatile(
        "mma.sync.aligned.m16n8k16.row.col.f32.bf16.bf16.f32 "
        "{%0,%1,%2,%3}, {%4,%5,%6,%7}, {%8,%9}, {%0,%1,%2,%3};"
        : "+f"(c[0]), "+f"(c[1]), "+f"(c[2]), "+f"(c[3])
        : "r"(a[0]), "r"(a[1]), "r"(a[2]), "r"(a[3]), "r"(b0), "r"(b1));
}
__device__ __forceinline__ uint32_t packbf(float lo, float hi) {
    uint32_t r;
    asm("cvt.rn.bf16x2.f32 %0, %1, %2;" : "=r"(r) : "f"(hi), "f"(lo));
    return r;
}

#define LDB 272            // smem bytes per 128-bf16 row (136 halves, conflict-free ldmatrix)

// ---------------------------------------------------------------------------
// Kernel 1: GroupNorm statistics only. One block per (b, group).
// ---------------------------------------------------------------------------
__global__ __launch_bounds__(256) void gnstat_kernel(const float* __restrict__ x) {
    __shared__ float rs[256], rs2[256];
    int tid = threadIdx.x;
    int b = blockIdx.x >> 5;
    int g = blockIdx.x & 31;
    const float4* xp = (const float4*)(x + ((size_t)b * C + g * CPG) * NSP);

    float s = 0.f, s2 = 0.f;
    for (int i = tid; i < CPG * NSP / 4; i += 256) {
        float4 v = xp[i];
        s  += v.x + v.y + v.z + v.w;
        s2 += v.x * v.x + v.y * v.y + v.z * v.z + v.w * v.w;
    }
    rs[tid] = s; rs2[tid] = s2;
    __syncthreads();
    #pragma unroll
    for (int off = 128; off > 0; off >>= 1) {
        if (tid < off) { rs[tid] += rs[tid + off]; rs2[tid] += rs2[tid + off]; }
        __syncthreads();
    }
    if (tid == 0) {
        const float invN = 1.0f / (CPG * NSP);
        float mean = rs[0] * invN;
        float var  = rs2[0] * invN - mean * mean;
        g_stat[blockIdx.x] = make_float2(mean, rsqrtf(var + 1e-5f));
    }
}

// ---------------------------------------------------------------------------
// Kernel 2: QKV projection, HMMA bf16, GN fused into staging.
// grid (32 s-tiles, B, role 0=q 1=k 2=v), 256 threads.
// Xs tile: xn [c=128][s=128] bf16 (GN applied). Ws tile: W [o=128][c=128] bf16.
// role q/k: A = Xs^T (ldsm trans, m=s,k=c), B = Ws (n=o,k=c) -> out (s,o)
// role v  : A = Ws (m=o,k=c),               B = Xs^T (n=s,k=c) -> out (o,s)
// ---------------------------------------------------------------------------
__global__ __launch_bounds__(256, 1) void qkv_kernel(const float* __restrict__ x,
                                                     const float* __restrict__ gw,
                                                     const float* __restrict__ gb,
                                                     const float* __restrict__ wq,
                                                     const float* __restrict__ bias) {
    extern __shared__ char smraw[];
    uint32_t smem = smem_u32(smraw);
    const uint32_t Xs = smem;                 // [c][s] bf16, LDB rows
    const uint32_t Ws = smem + 128 * LDB;     // [o][c] bf16

    int tid = threadIdx.x;
    int w = tid >> 5, t = tid & 31;
    int s0 = blockIdx.x * 128;
    int b  = blockIdx.y;
    int role = blockIdx.z;

    // stage xn tile [c][s] with GN applied
    for (int i = tid; i < 128 * 32; i += 256) {
        int c = i >> 5, s4 = i & 31;
        float2 st = g_stat[b * G + (c >> 2)];
        float wch = gw[c] * st.y;
        float bch = gb[c] - st.x * wch;
        float4 v = ((const float4*)(x + ((size_t)b * C + c) * NSP + s0))[s4];
        uint2 pk;
        pk.x = packbf(v.x * wch + bch, v.y * wch + bch);
        pk.y = packbf(v.z * wch + bch, v.w * wch + bch);
        *(uint2*)(smraw + c * LDB + s4 * 8) = pk;
    }
    // stage W tile [o][c]
    for (int i = tid; i < 128 * 32; i += 256) {
        int o = i >> 5, c4 = i & 31;
        float4 v = ((const float4*)(wq + (size_t)(role * 128 + o) * 128))[c4];
        uint2 pk;
        pk.x = packbf(v.x, v.y);
        pk.y = packbf(v.z, v.w);
        *(uint2*)(smraw + 128 * LDB + o * LDB + c4 * 8) = pk;
    }
    __syncthreads();

    float acc[16][4];
    #pragma unroll
    for (int n = 0; n < 16; n++) { acc[n][0] = acc[n][1] = acc[n][2] = acc[n][3] = 0.f; }

    if (role < 2) {
        // A = Xs^T: trans frags. row(k=c) = (t&7) + ((t>>4)&1)*8 (+j*16)
        //                        col(m=s) = w*16 + ((t>>3)&1)*8
        uint32_t af[8][4];
        uint32_t abase = Xs + (uint32_t)(((t & 7) + ((t >> 4) & 1) * 8) * LDB
                                         + (w * 16 + ((t >> 3) & 1) * 8) * 2);
        #pragma unroll
        for (int j = 0; j < 8; j++)
            ldsm4t(af[j][0], af[j][1], af[j][2], af[j][3], abase + j * (16 * LDB));

        // B = Ws: non-trans (n=o rows, k=c cols)
        uint32_t bbase = Ws + (uint32_t)(((t & 7) + ((t >> 4) << 3)) * LDB
                                         + ((t >> 3) & 1) * 16);
        #pragma unroll
        for (int n2 = 0; n2 < 8; n2++) {
            uint32_t baddr = bbase + n2 * (16 * LDB);
            #pragma unroll
            for (int j = 0; j < 8; j++) {
                uint32_t f0, f1, f2, f3;
                ldsm4(f0, f1, f2, f3, baddr + j * 32);
                mma16816(acc[2 * n2],     af[j], f0, f1);
                mma16816(acc[2 * n2 + 1], af[j], f2, f3);
            }
        }

        // epilogue: rows s = s0 + w*16 + (t>>2) (+8), cols o = n*8 + 2*(t&3)
        const float scale = 0.1275174331f;   // 128^-0.5 * log2(e)
        int r0 = s0 + w * 16 + (t >> 2), r1 = r0 + 8;
        __nv_bfloat16* dst = (role == 0) ? g_qh : g_kh;
        #pragma unroll
        for (int n = 0; n < 16; n++) {
            int col = n * 8 + 2 * (t & 3);
            float bv0 = bias[role * 128 + col];
            float bv1 = bias[role * 128 + col + 1];
            float v00 = acc[n][0] + bv0, v01 = acc[n][1] + bv1;
            float v10 = acc[n][2] + bv0, v11 = acc[n][3] + bv1;
            if (role == 0) { v00 *= scale; v01 *= scale; v10 *= scale; v11 *= scale; }
            *(uint32_t*)(dst + ((size_t)(b * NSP + r0) << 7) + col) = packbf(v00, v01);
            *(uint32_t*)(dst + ((size_t)(b * NSP + r1) << 7) + col) = packbf(v10, v11);
        }
    } else {
        // A = Ws: non-trans row-major (m=o, k=c)
        uint32_t af[8][4];
        uint32_t abase = Ws + (uint32_t)((w * 16 + (t & 7) + ((t >> 3) & 1) * 8) * LDB
                                         + (t >> 4) * 16);
        #pragma unroll
        for (int j = 0; j < 8; j++)
            ldsm4(af[j][0], af[j][1], af[j][2], af[j][3], abase + j * 32);

        // B = Xs^T: trans frags. row(k=c) = (t&7) + ((t>>3)&1)*8 (+j*16)
        //                        col(n=s) = n2*16 + ((t>>4)&1)*8
        uint32_t bbase = Xs + (uint32_t)(((t & 7) + ((t >> 3) & 1) * 8) * LDB
                                         + (((t >> 4) & 1) * 8) * 2);
        #pragma unroll
        for (int n2 = 0; n2 < 8; n2++) {
            uint32_t baddr = bbase + n2 * 32;          // 16 cols * 2B
            #pragma unroll
            for (int j = 0; j < 8; j++) {
                uint32_t f0, f1, f2, f3;
                ldsm4t(f0, f1, f2, f3, baddr + j * (16 * LDB));
                mma16816(acc[2 * n2],     af[j], f0, f1);
                mma16816(acc[2 * n2 + 1], af[j], f2, f3);
            }
        }

        // epilogue: rows o = w*16 + (t>>2) (+8), cols s = n*8 + 2*(t&3)
        int o0 = w * 16 + (t >> 2), o1 = o0 + 8;
        float bv0 = bias[256 + o0], bv1 = bias[256 + o1];
        #pragma unroll
        for (int n = 0; n < 16; n++) {
            int col = n * 8 + 2 * (t & 3);
            *(uint32_t*)(g_vt + ((size_t)(b * C + o0) << 12) + s0 + col) =
                packbf(acc[n][0] + bv0, acc[n][1] + bv0);
            *(uint32_t*)(g_vt + ((size_t)(b * C + o1) << 12) + s0 + col) =
                packbf(acc[n][2] + bv1, acc[n][3] + bv1);
        }
    }
}

// ---------------------------------------------------------------------------
// Kernel 3: flash attention with mma.sync (HMMA) bf16. (unchanged core)
// ---------------------------------------------------------------------------
#define SM_ATTN (3 * 128 * LDB)      // Q, K, V tiles

__global__ __launch_bounds__(256, 1) void attn_kernel() {
    extern __shared__ char smraw[];
    uint32_t smem = smem_u32(smraw);
    const uint32_t Qs = smem;
    const uint32_t Ks = smem + 128 * LDB;
    const uint32_t Vs = smem + 2 * 128 * LDB;

    int tid = threadIdx.x;
    int w = tid >> 5, t = tid & 31;
    int b = blockIdx.y, q0 = blockIdx.x * 128;

    {
        const uint4* src = (const uint4*)(g_qh + ((size_t)(b * NSP + q0) << 7));
        for (int i = tid; i < 2048; i += 256) {
            int r = i >> 4, c = i & 15;
            *(uint4*)(smraw + r * LDB + c * 16) = src[i];
        }
    }
    __syncthreads();

    uint32_t qf[8][4];
    {
        uint32_t qbase = Qs + (uint32_t)((w * 16 + (t & 7) + ((t >> 3) & 1) * 8) * LDB
                                         + (t >> 4) * 16);
        #pragma unroll
        for (int j = 0; j < 8; j++)
            ldsm4(qf[j][0], qf[j][1], qf[j][2], qf[j][3], qbase + j * 32);
    }

    uint32_t kvoff = (uint32_t)(((t & 7) + ((t >> 4) << 3)) * LDB + ((t >> 3) & 1) * 16);
    uint32_t kb = Ks + kvoff, vb = Vs + kvoff;

    float O[16][4];
    #pragma unroll
    for (int n = 0; n < 16; n++) { O[n][0] = O[n][1] = O[n][2] = O[n][3] = 0.f; }
    float m0 = -1e30f, m1 = -1e30f, l0r = 0.f, l1r = 0.f;

    for (int kt = 0; kt < NSP / 128; kt++) {
        __syncthreads();
        const uint4* ksrc = (const uint4*)(g_kh + ((size_t)(b * NSP + kt * 128) << 7));
        for (int i = tid; i < 2048; i += 256) {
            int r = i >> 4, c = i & 15;
            *(uint4*)(smraw + 128 * LDB + r * LDB + c * 16) = ksrc[i];
        }
        for (int i = tid; i < 2048; i += 256) {
            int r = i >> 4, c = i & 15;
            const uint4* vsrc = (const uint4*)(g_vt + ((size_t)(b * C + r) << 12) + (kt << 7));
            *(uint4*)(smraw + 2 * 128 * LDB + r * LDB + c * 16) = vsrc[c];
        }
        __syncthreads();

        float S[16][4];
        #pragma unroll
        for (int n = 0; n < 16; n++) { S[n][0] = S[n][1] = S[n][2] = S[n][3] = 0.f; }
        #pragma unroll
        for (int n2 = 0; n2 < 8; n2++) {
            uint32_t kaddr = kb + n2 * (16 * LDB);
            #pragma unroll
            for (int j = 0; j < 8; j++) {
                uint32_t f0, f1, f2, f3;
                ldsm4(f0, f1, f2, f3, kaddr + j * 32);
                mma16816(S[2 * n2],     qf[j], f0, f1);
                mma16816(S[2 * n2 + 1], qf[j], f2, f3);
            }
        }

        float mx0 = -1e30f, mx1 = -1e30f;
        #pragma unroll
        for (int n = 0; n < 16; n++) {
            mx0 = fmaxf(mx0, fmaxf(S[n][0], S[n][1]));
            mx1 = fmaxf(mx1, fmaxf(S[n][2], S[n][3]));
        }
        mx0 = fmaxf(mx0, __shfl_xor_sync(0xffffffffu, mx0, 1));
        mx0 = fmaxf(mx0, __shfl_xor_sync(0xffffffffu, mx0, 2));
        mx1 = fmaxf(mx1, __shfl_xor_sync(0xffffffffu, mx1, 1));
        mx1 = fmaxf(mx1, __shfl_xor_sync(0xffffffffu, mx1, 2));
        float mn0 = fmaxf(m0, mx0), mn1 = fmaxf(m1, mx1);
        float a0 = exp2f(m0 - mn0), a1 = exp2f(m1 - mn1);
        m0 = mn0; m1 = mn1;

        float s0 = 0.f, s1 = 0.f;
        #pragma unroll
        for (int n = 0; n < 16; n++) {
            S[n][0] = exp2f(S[n][0] - mn0);
            S[n][1] = exp2f(S[n][1] - mn0);
            S[n][2] = exp2f(S[n][2] - mn1);
            S[n][3] = exp2f(S[n][3] - mn1);
            s0 += S[n][0] + S[n][1];
            s1 += S[n][2] + S[n][3];
        }
        s0 += __shfl_xor_sync(0xffffffffu, s0, 1);
        s0 += __shfl_xor_sync(0xffffffffu, s0, 2);
        s1 += __shfl_xor_sync(0xffffffffu, s1, 1);
        s1 += __shfl_xor_sync(0xffffffffu, s1, 2);
        l0r = l0r * a0 + s0;
        l1r = l1r * a1 + s1;

        #pragma unroll
        for (int n = 0; n < 16; n++) {
            O[n][0] *= a0; O[n][1] *= a0; O[n][2] *= a1; O[n][3] *= a1;
        }

        #pragma unroll
        for (int j = 0; j < 8; j++) {
            uint32_t pa[4];
            pa[0] = packbf(S[2 * j][0],     S[2 * j][1]);
            pa[1] = packbf(S[2 * j][2],     S[2 * j][3]);
            pa[2] = packbf(S[2 * j + 1][0], S[2 * j + 1][1]);
            pa[3] = packbf(S[2 * j + 1][2], S[2 * j + 1][3]);
            uint32_t vaddr = vb + j * 32;
            #pragma unroll
            for (int d2 = 0; d2 < 8; d2++) {
                uint32_t f0, f1, f2, f3;
                ldsm4(f0, f1, f2, f3, vaddr + d2 * (16 * LDB));
                mma16816(O[2 * d2],     pa, f0, f1);
                mma16816(O[2 * d2 + 1], pa, f2, f3);
            }
        }
    }

    // epilogue: normalize, store bf16 (b, q0+row, d)
    float r0 = 1.0f / l0r, r1 = 1.0f / l1r;
    int g = t >> 2, tg = t & 3;
    __nv_bfloat16* dst0 = g_aoh + ((size_t)(b * NSP + q0 + w * 16 + g) << 7) + tg * 2;
    __nv_bfloat16* dst1 = dst0 + (8 << 7);
    #pragma unroll
    for (int n = 0; n < 16; n++) {
        *(uint32_t*)(dst0 + n * 8) = packbf(O[n][0] * r0, O[n][1] * r0);
        *(uint32_t*)(dst1 + n * 8) = packbf(O[n][2] * r1, O[n][3] * r1);
    }
}

// ---------------------------------------------------------------------------
// Kernel 4: out projection HMMA + bias + residual. grid (32 s-tiles, B).
// A = out_w [o][c] (m=o), B = ao [s][c] (n=s). out (b,o,s) fp32.
// ---------------------------------------------------------------------------
__global__ __launch_bounds__(256, 1) void oproj_kernel(const float* __restrict__ wo,
                                                       const float* __restrict__ bias,
                                                       const float* __restrict__ x,
                                                       float* __restrict__ out) {
    extern __shared__ char smraw[];
    uint32_t smem = smem_u32(smraw);
    const uint32_t As = smem;                 // ao tile [s][c] bf16
    const uint32_t Ws = smem + 128 * LDB;     // W tile [o][c] bf16

    int tid = threadIdx.x;
    int w = tid >> 5, t = tid & 31;
    int s0 = blockIdx.x * 128;
    int b  = blockIdx.y;

    for (int i = tid; i < 128 * 16; i += 256) {
        int r = i >> 4, c8 = i & 15;
        uint4 v = ((const uint4*)(g_aoh + ((size_t)(b * NSP + s0 + r) << 7)))[c8];
        *(uint4*)(smraw + r * LDB + c8 * 16) = v;
    }
    for (int i = tid; i < 128 * 32; i += 256) {
        int o = i >> 5, c4 = i & 31;
        float4 v = ((const float4*)(wo + (size_t)o * 128))[c4];
        uint2 pk;
        pk.x = packbf(v.x, v.y);
        pk.y = packbf(v.z, v.w);
        *(uint2*)(smraw + 128 * LDB + o * LDB + c4 * 8) = pk;
    }
    __syncthreads();

    // A = Ws rows (m=o)
    uint32_t af[8][4];
    uint32_t abase = Ws + (uint32_t)((w * 16 + (t & 7) + ((t >> 3) & 1) * 8) * LDB
                                     + (t >> 4) * 16);
    #pragma unroll
    for (int j = 0; j < 8; j++)
        ldsm4(af[j][0], af[j][1], af[j][2], af[j][3], abase + j * 32);

    float acc[16][4];
    #pragma unroll
    for (int n = 0; n < 16; n++) { acc[n][0] = acc[n][1] = acc[n][2] = acc[n][3] = 0.f; }

    uint32_t bbase = As + (uint32_t)(((t & 7) + ((t >> 4) << 3)) * LDB
                                     + ((t >> 3) & 1) * 16);
    #pragma unroll
    for (int n2 = 0; n2 < 8; n2++) {
        uint32_t baddr = bbase + n2 * (16 * LDB);
        #pragma unroll
        for (int j = 0; j < 8; j++) {
            uint32_t f0, f1, f2, f3;
            ldsm4(f0, f1, f2, f3, baddr + j * 32);
            mma16816(acc[2 * n2],     af[j], f0, f1);
            mma16816(acc[2 * n2 + 1], af[j], f2, f3);
        }
    }

    // epilogue: rows o, cols s; += bias + residual, fp32 store
    int o0 = w * 16 + (t >> 2), o1 = o0 + 8;
    float bv0 = bias[o0], bv1 = bias[o1];
    #pragma unroll
    for (int n = 0; n < 16; n++) {
        int col = n * 8 + 2 * (t & 3);
        size_t base0 = ((size_t)(b * C + o0) << 12) + s0 + col;
        size_t base1 = ((size_t)(b * C + o1) << 12) + s0 + col;
        float2 xv0 = *(const float2*)(x + base0);
        float2 xv1 = *(const float2*)(x + base1);
        *(float2*)(out + base0) = make_float2(acc[n][0] + bv0 + xv0.x,
                                              acc[n][1] + bv0 + xv0.y);
        *(float2*)(out + base1) = make_float2(acc[n][2] + bv1 + xv1.x,
                                              acc[n][3] + bv1 + xv1.y);
    }
}

// ---------------------------------------------------------------------------
extern "C" void kernel_launch(void* const* d_in, const int* in_sizes, int n_in,
                              void* d_out, int out_size) {
    const float* x     = (const float*)d_in[0];
    const float* gn_w  = (const float*)d_in[1];
    const float* gn_b  = (const float*)d_in[2];
    const float* qkv_w = (const float*)d_in[3];
    const float* qkv_b = (const float*)d_in[4];
    const float* out_w = (const float*)d_in[5];
    const float* out_b = (const float*)d_in[6];
    float* out = (float*)d_out;

    static bool attrs_set = false;
    const int tile2_smem = 2 * 128 * LDB;     // 69632 B
    if (!attrs_set) {
        cudaFuncSetAttribute(qkv_kernel,   cudaFuncAttributeMaxDynamicSharedMemorySize, tile2_smem);
        cudaFuncSetAttribute(oproj_kernel, cudaFuncAttributeMaxDynamicSharedMemorySize, tile2_smem);
        cudaFuncSetAttribute(attn_kernel,  cudaFuncAttributeMaxDynamicSharedMemorySize, SM_ATTN);
        attrs_set = true;
    }

    gnstat_kernel<<<B * G, 256>>>(x);
    qkv_kernel<<<dim3(NSP / 128, B, 3), 256, tile2_smem>>>(x, gn_w, gn_b, qkv_w, qkv_b);
    attn_kernel<<<dim3(NSP / 128, B), 256, SM_ATTN>>>();
    oproj_kernel<<<dim3(NSP / 128, B), 256, tile2_smem>>>(out_w, out_b, x, out);
}

// round 8
// speedup vs baseline: 12.0879x; 1.2116x over previous
#include <cuda_runtime.h>
#include <cuda_bf16.h>
#include <math.h>
#include <cstdint>

// Problem constants
#define B 4
#define C 128
#define NSP 4096          // H*W*D
#define G 32
#define CPG 4             // C / G
#define DH 128

// Scratch (allocation-free rule: __device__ globals)
__device__ float2 g_stat[B * G];                 // per (b,g): mean, rstd
__device__ __nv_bfloat16 g_qh[B * NSP * C];      // (b,n,c), pre-scaled by c^-0.5*log2(e)
__device__ __nv_bfloat16 g_kh[B * NSP * C];      // (b,n,c)
__device__ __nv_bfloat16 g_vt[B * C * NSP];      // (b,c,n)  transposed V
__device__ __nv_bfloat16 g_aoh[B * NSP * C];     // attention output (b,n,c) bf16

// ---------------------------------------------------------------------------
// helpers
// ---------------------------------------------------------------------------
__device__ __forceinline__ uint32_t smem_u32(const void* p) {
    uint32_t a;
    asm("{ .reg .u64 t; cvta.to.shared.u64 t, %1; cvt.u32.u64 %0, t; }"
        : "=r"(a) : "l"(p));
    return a;
}
__device__ __forceinline__ void ldsm4(uint32_t& r0, uint32_t& r1, uint32_t& r2,
                                      uint32_t& r3, uint32_t addr) {
    asm volatile("ldmatrix.sync.aligned.m8n8.x4.shared.b16 {%0,%1,%2,%3}, [%4];"
        : "=r"(r0), "=r"(r1), "=r"(r2), "=r"(r3) : "r"(addr));
}
__device__ __forceinline__ void ldsm4t(uint32_t& r0, uint32_t& r1, uint32_t& r2,
                                       uint32_t& r3, uint32_t addr) {
    asm volatile("ldmatrix.sync.aligned.m8n8.x4.trans.shared.b16 {%0,%1,%2,%3}, [%4];"
        : "=r"(r0), "=r"(r1), "=r"(r2), "=r"(r3) : "r"(addr));
}
__device__ __forceinline__ void mma16816(float* c, const uint32_t* a,
                                         uint32_t b0, uint32_t b1) {
    asm volatile(
        "mma.sync.aligned.m16n8k16.row.col.f32.bf16.bf16.f32 "
        "{%0,%1,%2,%3}, {%4,%5,%6,%7}, {%8,%9}, {%0,%1,%2,%3};"
        : "+f"(c[0]), "+f"(c[1]), "+f"(c[2]), "+f"(c[3])
        : "r"(a[0]), "r"(a[1]), "r"(a[2]), "r"(a[3]), "r"(b0), "r"(b1));
}
__device__ __forceinline__ uint32_t packbf(float lo, float hi) {
    uint32_t r;
    asm("cvt.rn.bf16x2.f32 %0, %1, %2;" : "=r"(r) : "f"(hi), "f"(lo));
    return r;
}
__device__ __forceinline__ void cpasync16(uint32_t dst, const void* src) {
    asm volatile("cp.async.cg.shared.global [%0], [%1], 16;" :: "r"(dst), "l"(src));
}
#define CP_COMMIT()  asm volatile("cp.async.commit_group;" ::: "memory")
#define CP_WAIT(n)   asm volatile("cp.async.wait_group %0;" :: "n"(n) : "memory")

#define LDB 272            // smem bytes per 128-bf16 row (136 halves, conflict-free ldmatrix)
#define TILE (128 * LDB)

// ---------------------------------------------------------------------------
// Kernel 1: GroupNorm statistics only. One block per (b, group).
// ---------------------------------------------------------------------------
__global__ __launch_bounds__(256) void gnstat_kernel(const float* __restrict__ x) {
    __shared__ float rs[256], rs2[256];
    int tid = threadIdx.x;
    int b = blockIdx.x >> 5;
    int g = blockIdx.x & 31;
    const float4* xp = (const float4*)(x + ((size_t)b * C + g * CPG) * NSP);

    float s = 0.f, s2 = 0.f;
    for (int i = tid; i < CPG * NSP / 4; i += 256) {
        float4 v = xp[i];
        s  += v.x + v.y + v.z + v.w;
        s2 += v.x * v.x + v.y * v.y + v.z * v.z + v.w * v.w;
    }
    rs[tid] = s; rs2[tid] = s2;
    __syncthreads();
    #pragma unroll
    for (int off = 128; off > 0; off >>= 1) {
        if (tid < off) { rs[tid] += rs[tid + off]; rs2[tid] += rs2[tid + off]; }
        __syncthreads();
    }
    if (tid == 0) {
        const float invN = 1.0f / (CPG * NSP);
        float mean = rs[0] * invN;
        float var  = rs2[0] * invN - mean * mean;
        g_stat[blockIdx.x] = make_float2(mean, rsqrtf(var + 1e-5f));
    }
}

// ---------------------------------------------------------------------------
// Kernel 2: QKV projection, HMMA bf16, GN fused into staging.
// ---------------------------------------------------------------------------
__global__ __launch_bounds__(256, 1) void qkv_kernel(const float* __restrict__ x,
                                                     const float* __restrict__ gw,
                                                     const float* __restrict__ gb,
                                                     const float* __restrict__ wq,
                                                     const float* __restrict__ bias) {
    extern __shared__ char smraw[];
    uint32_t smem = smem_u32(smraw);
    const uint32_t Xs = smem;                 // [c][s] bf16, LDB rows
    const uint32_t Ws = smem + TILE;          // [o][c] bf16

    int tid = threadIdx.x;
    int w = tid >> 5, t = tid & 31;
    int s0 = blockIdx.x * 128;
    int b  = blockIdx.y;
    int role = blockIdx.z;

    for (int i = tid; i < 128 * 32; i += 256) {
        int c = i >> 5, s4 = i & 31;
        float2 st = g_stat[b * G + (c >> 2)];
        float wch = gw[c] * st.y;
        float bch = gb[c] - st.x * wch;
        float4 v = ((const float4*)(x + ((size_t)b * C + c) * NSP + s0))[s4];
        uint2 pk;
        pk.x = packbf(v.x * wch + bch, v.y * wch + bch);
        pk.y = packbf(v.z * wch + bch, v.w * wch + bch);
        *(uint2*)(smraw + c * LDB + s4 * 8) = pk;
    }
    for (int i = tid; i < 128 * 32; i += 256) {
        int o = i >> 5, c4 = i & 31;
        float4 v = ((const float4*)(wq + (size_t)(role * 128 + o) * 128))[c4];
        uint2 pk;
        pk.x = packbf(v.x, v.y);
        pk.y = packbf(v.z, v.w);
        *(uint2*)(smraw + TILE + o * LDB + c4 * 8) = pk;
    }
    __syncthreads();

    float acc[16][4];
    #pragma unroll
    for (int n = 0; n < 16; n++) { acc[n][0] = acc[n][1] = acc[n][2] = acc[n][3] = 0.f; }

    if (role < 2) {
        uint32_t af[8][4];
        uint32_t abase = Xs + (uint32_t)(((t & 7) + ((t >> 4) & 1) * 8) * LDB
                                         + (w * 16 + ((t >> 3) & 1) * 8) * 2);
        #pragma unroll
        for (int j = 0; j < 8; j++)
            ldsm4t(af[j][0], af[j][1], af[j][2], af[j][3], abase + j * (16 * LDB));

        uint32_t bbase = Ws + (uint32_t)(((t & 7) + ((t >> 4) << 3)) * LDB
                                         + ((t >> 3) & 1) * 16);
        #pragma unroll
        for (int n2 = 0; n2 < 8; n2++) {
            uint32_t baddr = bbase + n2 * (16 * LDB);
            #pragma unroll
            for (int j = 0; j < 8; j++) {
                uint32_t f0, f1, f2, f3;
                ldsm4(f0, f1, f2, f3, baddr + j * 32);
                mma16816(acc[2 * n2],     af[j], f0, f1);
                mma16816(acc[2 * n2 + 1], af[j], f2, f3);
            }
        }

        const float scale = 0.1275174331f;   // 128^-0.5 * log2(e)
        int r0 = s0 + w * 16 + (t >> 2), r1 = r0 + 8;
        __nv_bfloat16* dst = (role == 0) ? g_qh : g_kh;
        #pragma unroll
        for (int n = 0; n < 16; n++) {
            int col = n * 8 + 2 * (t & 3);
            float bv0 = bias[role * 128 + col];
            float bv1 = bias[role * 128 + col + 1];
            float v00 = acc[n][0] + bv0, v01 = acc[n][1] + bv1;
            float v10 = acc[n][2] + bv0, v11 = acc[n][3] + bv1;
            if (role == 0) { v00 *= scale; v01 *= scale; v10 *= scale; v11 *= scale; }
            *(uint32_t*)(dst + ((size_t)(b * NSP + r0) << 7) + col) = packbf(v00, v01);
            *(uint32_t*)(dst + ((size_t)(b * NSP + r1) << 7) + col) = packbf(v10, v11);
        }
    } else {
        uint32_t af[8][4];
        uint32_t abase = Ws + (uint32_t)((w * 16 + (t & 7) + ((t >> 3) & 1) * 8) * LDB
                                         + (t >> 4) * 16);
        #pragma unroll
        for (int j = 0; j < 8; j++)
            ldsm4(af[j][0], af[j][1], af[j][2], af[j][3], abase + j * 32);

        uint32_t bbase = Xs + (uint32_t)(((t & 7) + ((t >> 3) & 1) * 8) * LDB
                                         + (((t >> 4) & 1) * 8) * 2);
        #pragma unroll
        for (int n2 = 0; n2 < 8; n2++) {
            uint32_t baddr = bbase + n2 * 32;
            #pragma unroll
            for (int j = 0; j < 8; j++) {
                uint32_t f0, f1, f2, f3;
                ldsm4t(f0, f1, f2, f3, baddr + j * (16 * LDB));
                mma16816(acc[2 * n2],     af[j], f0, f1);
                mma16816(acc[2 * n2 + 1], af[j], f2, f3);
            }
        }

        int o0 = w * 16 + (t >> 2), o1 = o0 + 8;
        float bv0 = bias[256 + o0], bv1 = bias[256 + o1];
        #pragma unroll
        for (int n = 0; n < 16; n++) {
            int col = n * 8 + 2 * (t & 3);
            *(uint32_t*)(g_vt + ((size_t)(b * C + o0) << 12) + s0 + col) =
                packbf(acc[n][0] + bv0, acc[n][1] + bv0);
            *(uint32_t*)(g_vt + ((size_t)(b * C + o1) << 12) + s0 + col) =
                packbf(acc[n][2] + bv1, acc[n][3] + bv1);
        }
    }
}

// ---------------------------------------------------------------------------
// Kernel 3: flash attention, HMMA bf16, 2-stage cp.async K/V pipeline.
// smem: Q | K0 | V0 | K1 | V1  (5 tiles)
// ---------------------------------------------------------------------------
#define SM_ATTN (5 * TILE)

__global__ __launch_bounds__(256, 1) void attn_kernel() {
    extern __shared__ char smraw[];
    uint32_t smem = smem_u32(smraw);
    const uint32_t Qs = smem;

    int tid = threadIdx.x;
    int w = tid >> 5, t = tid & 31;
    int b = blockIdx.y, q0 = blockIdx.x * 128;

    // per-thread staging indices (8 chunks of 16B per tile)
    int sr = tid >> 4, sc = tid & 15;      // rows sr, sr+16, ..., sr+112; col chunk sc

    // stage Q tile via cp.async
    {
        const char* qsrc = (const char*)(g_qh + ((size_t)(b * NSP + q0) << 7));
        #pragma unroll
        for (int rr = 0; rr < 8; rr++) {
            int r = sr + rr * 16;
            cpasync16(Qs + r * LDB + sc * 16, qsrc + r * 256 + sc * 16);
        }
    }
    CP_COMMIT();

    // issue K/V tile 0 into buffer 0
    const char* kbase = (const char*)(g_kh + ((size_t)b * NSP << 7));
    const char* vbase = (const char*)(g_vt + ((size_t)b * C << 12));
    #pragma unroll
    for (int rr = 0; rr < 8; rr++) {
        int r = sr + rr * 16;
        cpasync16(smem + TILE + r * LDB + sc * 16, kbase + r * 256 + sc * 16);
        cpasync16(smem + 2 * TILE + r * LDB + sc * 16, vbase + (size_t)r * 8192 + sc * 16);
    }
    CP_COMMIT();

    // wait for Q (allow K/V group 0 outstanding), load Q fragments
    CP_WAIT(1);
    __syncthreads();
    uint32_t qf[8][4];
    {
        uint32_t qbase = Qs + (uint32_t)((w * 16 + (t & 7) + ((t >> 3) & 1) * 8) * LDB
                                         + (t >> 4) * 16);
        #pragma unroll
        for (int j = 0; j < 8; j++)
            ldsm4(qf[j][0], qf[j][1], qf[j][2], qf[j][3], qbase + j * 32);
    }

    uint32_t kvoff = (uint32_t)(((t & 7) + ((t >> 4) << 3)) * LDB + ((t >> 3) & 1) * 16);

    float O[16][4];
    #pragma unroll
    for (int n = 0; n < 16; n++) { O[n][0] = O[n][1] = O[n][2] = O[n][3] = 0.f; }
    float m0 = -1e30f, m1 = -1e30f, l0r = 0.f, l1r = 0.f;

    for (int kt = 0; kt < NSP / 128; kt++) {
        int cur = kt & 1;
        if (kt + 1 < NSP / 128) {
            __syncthreads();   // all warps done computing on buffer cur^1 (iter kt-1)
            int nb = cur ^ 1;
            #pragma unroll
            for (int rr = 0; rr < 8; rr++) {
                int r = sr + rr * 16;
                cpasync16(smem + (1 + 2 * nb) * TILE + r * LDB + sc * 16,
                          kbase + (size_t)(kt + 1) * 32768 + r * 256 + sc * 16);
                cpasync16(smem + (2 + 2 * nb) * TILE + r * LDB + sc * 16,
                          vbase + (size_t)r * 8192 + (size_t)(kt + 1) * 256 + sc * 16);
            }
            CP_COMMIT();
            CP_WAIT(1);        // current tile's group complete
        } else {
            CP_WAIT(0);
        }
        __syncthreads();

        uint32_t kb = smem + (1 + 2 * cur) * TILE + kvoff;
        uint32_t vb = smem + (2 + 2 * cur) * TILE + kvoff;

        float S[16][4];
        #pragma unroll
        for (int n = 0; n < 16; n++) { S[n][0] = S[n][1] = S[n][2] = S[n][3] = 0.f; }
        #pragma unroll
        for (int n2 = 0; n2 < 8; n2++) {
            uint32_t kaddr = kb + n2 * (16 * LDB);
            #pragma unroll
            for (int j = 0; j < 8; j++) {
                uint32_t f0, f1, f2, f3;
                ldsm4(f0, f1, f2, f3, kaddr + j * 32);
                mma16816(S[2 * n2],     qf[j], f0, f1);
                mma16816(S[2 * n2 + 1], qf[j], f2, f3);
            }
        }

        float mx0 = -1e30f, mx1 = -1e30f;
        #pragma unroll
        for (int n = 0; n < 16; n++) {
            mx0 = fmaxf(mx0, fmaxf(S[n][0], S[n][1]));
            mx1 = fmaxf(mx1, fmaxf(S[n][2], S[n][3]));
        }
        mx0 = fmaxf(mx0, __shfl_xor_sync(0xffffffffu, mx0, 1));
        mx0 = fmaxf(mx0, __shfl_xor_sync(0xffffffffu, mx0, 2));
        mx1 = fmaxf(mx1, __shfl_xor_sync(0xffffffffu, mx1, 1));
        mx1 = fmaxf(mx1, __shfl_xor_sync(0xffffffffu, mx1, 2));
        float mn0 = fmaxf(m0, mx0), mn1 = fmaxf(m1, mx1);
        float a0 = exp2f(m0 - mn0), a1 = exp2f(m1 - mn1);
        m0 = mn0; m1 = mn1;

        float s0 = 0.f, s1 = 0.f;
        #pragma unroll
        for (int n = 0; n < 16; n++) {
            S[n][0] = exp2f(S[n][0] - mn0);
            S[n][1] = exp2f(S[n][1] - mn0);
            S[n][2] = exp2f(S[n][2] - mn1);
            S[n][3] = exp2f(S[n][3] - mn1);
            s0 += S[n][0] + S[n][1];
            s1 += S[n][2] + S[n][3];
        }
        s0 += __shfl_xor_sync(0xffffffffu, s0, 1);
        s0 += __shfl_xor_sync(0xffffffffu, s0, 2);
        s1 += __shfl_xor_sync(0xffffffffu, s1, 1);
        s1 += __shfl_xor_sync(0xffffffffu, s1, 2);
        l0r = l0r * a0 + s0;
        l1r = l1r * a1 + s1;

        #pragma unroll
        for (int n = 0; n < 16; n++) {
            O[n][0] *= a0; O[n][1] *= a0; O[n][2] *= a1; O[n][3] *= a1;
        }

        #pragma unroll
        for (int j = 0; j < 8; j++) {
            uint32_t pa[4];
            pa[0] = packbf(S[2 * j][0],     S[2 * j][1]);
            pa[1] = packbf(S[2 * j][2],     S[2 * j][3]);
            pa[2] = packbf(S[2 * j + 1][0], S[2 * j + 1][1]);
            pa[3] = packbf(S[2 * j + 1][2], S[2 * j + 1][3]);
            uint32_t vaddr = vb + j * 32;
            #pragma unroll
            for (int d2 = 0; d2 < 8; d2++) {
                uint32_t f0, f1, f2, f3;
                ldsm4(f0, f1, f2, f3, vaddr + d2 * (16 * LDB));
                mma16816(O[2 * d2],     pa, f0, f1);
                mma16816(O[2 * d2 + 1], pa, f2, f3);
            }
        }
    }

    // epilogue: normalize, store bf16 (b, q0+row, d)
    float r0 = 1.0f / l0r, r1 = 1.0f / l1r;
    int g = t >> 2, tg = t & 3;
    __nv_bfloat16* dst0 = g_aoh + ((size_t)(b * NSP + q0 + w * 16 + g) << 7) + tg * 2;
    __nv_bfloat16* dst1 = dst0 + (8 << 7);
    #pragma unroll
    for (int n = 0; n < 16; n++) {
        *(uint32_t*)(dst0 + n * 8) = packbf(O[n][0] * r0, O[n][1] * r0);
        *(uint32_t*)(dst1 + n * 8) = packbf(O[n][2] * r1, O[n][3] * r1);
    }
}

// ---------------------------------------------------------------------------
// Kernel 4: out projection HMMA + bias + residual.
// ---------------------------------------------------------------------------
__global__ __launch_bounds__(256, 1) void oproj_kernel(const float* __restrict__ wo,
                                                       const float* __restrict__ bias,
                                                       const float* __restrict__ x,
                                                       float* __restrict__ out) {
    extern __shared__ char smraw[];
    uint32_t smem = smem_u32(smraw);
    const uint32_t As = smem;
    const uint32_t Ws = smem + TILE;

    int tid = threadIdx.x;
    int w = tid >> 5, t = tid & 31;
    int s0 = blockIdx.x * 128;
    int b  = blockIdx.y;

    for (int i = tid; i < 128 * 16; i += 256) {
        int r = i >> 4, c8 = i & 15;
        uint4 v = ((const uint4*)(g_aoh + ((size_t)(b * NSP + s0 + r) << 7)))[c8];
        *(uint4*)(smraw + r * LDB + c8 * 16) = v;
    }
    for (int i = tid; i < 128 * 32; i += 256) {
        int o = i >> 5, c4 = i & 31;
        float4 v = ((const float4*)(wo + (size_t)o * 128))[c4];
        uint2 pk;
        pk.x = packbf(v.x, v.y);
        pk.y = packbf(v.z, v.w);
        *(uint2*)(smraw + TILE + o * LDB + c4 * 8) = pk;
    }
    __syncthreads();

    uint32_t af[8][4];
    uint32_t abase = Ws + (uint32_t)((w * 16 + (t & 7) + ((t >> 3) & 1) * 8) * LDB
                                     + (t >> 4) * 16);
    #pragma unroll
    for (int j = 0; j < 8; j++)
        ldsm4(af[j][0], af[j][1], af[j][2], af[j][3], abase + j * 32);

    float acc[16][4];
    #pragma unroll
    for (int n = 0; n < 16; n++) { acc[n][0] = acc[n][1] = acc[n][2] = acc[n][3] = 0.f; }

    uint32_t bbase = As + (uint32_t)(((t & 7) + ((t >> 4) << 3)) * LDB
                                     + ((t >> 3) & 1) * 16);
    #pragma unroll
    for (int n2 = 0; n2 < 8; n2++) {
        uint32_t baddr = bbase + n2 * (16 * LDB);
        #pragma unroll
        for (int j = 0; j < 8; j++) {
            uint32_t f0, f1, f2, f3;
            ldsm4(f0, f1, f2, f3, baddr + j * 32);
            mma16816(acc[2 * n2],     af[j], f0, f1);
            mma16816(acc[2 * n2 + 1], af[j], f2, f3);
        }
    }

    int o0 = w * 16 + (t >> 2), o1 = o0 + 8;
    float bv0 = bias[o0], bv1 = bias[o1];
    #pragma unroll
    for (int n = 0; n < 16; n++) {
        int col = n * 8 + 2 * (t & 3);
        size_t base0 = ((size_t)(b * C + o0) << 12) + s0 + col;
        size_t base1 = ((size_t)(b * C + o1) << 12) + s0 + col;
        float2 xv0 = *(const float2*)(x + base0);
        float2 xv1 = *(const float2*)(x + base1);
        *(float2*)(out + base0) = make_float2(acc[n][0] + bv0 + xv0.x,
                                              acc[n][1] + bv0 + xv0.y);
        *(float2*)(out + base1) = make_float2(acc[n][2] + bv1 + xv1.x,
                                              acc[n][3] + bv1 + xv1.y);
    }
}

// ---------------------------------------------------------------------------
extern "C" void kernel_launch(void* const* d_in, const int* in_sizes, int n_in,
                              void* d_out, int out_size) {
    const float* x     = (const float*)d_in[0];
    const float* gn_w  = (const float*)d_in[1];
    const float* gn_b  = (const float*)d_in[2];
    const float* qkv_w = (const float*)d_in[3];
    const float* qkv_b = (const float*)d_in[4];
    const float* out_w = (const float*)d_in[5];
    const float* out_b = (const float*)d_in[6];
    float* out = (float*)d_out;

    static bool attrs_set = false;
    const int tile2_smem = 2 * TILE;
    if (!attrs_set) {
        cudaFuncSetAttribute(qkv_kernel,   cudaFuncAttributeMaxDynamicSharedMemorySize, tile2_smem);
        cudaFuncSetAttribute(oproj_kernel, cudaFuncAttributeMaxDynamicSharedMemorySize, tile2_smem);
        cudaFuncSetAttribute(attn_kernel,  cudaFuncAttributeMaxDynamicSharedMemorySize, SM_ATTN);
        attrs_set = true;
    }

    gnstat_kernel<<<B * G, 256>>>(x);
    qkv_kernel<<<dim3(NSP / 128, B, 3), 256, tile2_smem>>>(x, gn_w, gn_b, qkv_w, qkv_b);
    attn_kernel<<<dim3(NSP / 128, B), 256, SM_ATTN>>>();
    oproj_kernel<<<dim3(NSP / 128, B), 256, tile2_smem>>>(out_w, out_b, x, out);
}

// round 9
// speedup vs baseline: 12.9379x; 1.0703x over previous
#include <cuda_runtime.h>
#include <cuda_bf16.h>
#include <math.h>
#include <cstdint>

// Problem constants
#define B 4
#define C 128
#define NSP 4096          // H*W*D
#define G 32
#define CPG 4             // C / G
#define DH 128

// Scratch (allocation-free rule: __device__ globals)
__device__ float2 g_stat[B * G];                 // per (b,g): mean, rstd
__device__ __nv_bfloat16 g_qh[B * NSP * C];      // (b,n,c), pre-scaled by c^-0.5*log2(e)
__device__ __nv_bfloat16 g_kh[B * NSP * C];      // (b,n,c)
__device__ __nv_bfloat16 g_vt[B * C * NSP];      // (b,c,n)  transposed V
__device__ __nv_bfloat16 g_aoh[B * NSP * C];     // attention output (b,n,c) bf16

// ---------------------------------------------------------------------------
// helpers
// ---------------------------------------------------------------------------
__device__ __forceinline__ uint32_t smem_u32(const void* p) {
    uint32_t a;
    asm("{ .reg .u64 t; cvta.to.shared.u64 t, %1; cvt.u32.u64 %0, t; }"
        : "=r"(a) : "l"(p));
    return a;
}
__device__ __forceinline__ void ldsm4(uint32_t& r0, uint32_t& r1, uint32_t& r2,
                                      uint32_t& r3, uint32_t addr) {
    asm volatile("ldmatrix.sync.aligned.m8n8.x4.shared.b16 {%0,%1,%2,%3}, [%4];"
        : "=r"(r0), "=r"(r1), "=r"(r2), "=r"(r3) : "r"(addr));
}
__device__ __forceinline__ void ldsm4t(uint32_t& r0, uint32_t& r1, uint32_t& r2,
                                       uint32_t& r3, uint32_t addr) {
    asm volatile("ldmatrix.sync.aligned.m8n8.x4.trans.shared.b16 {%0,%1,%2,%3}, [%4];"
        : "=r"(r0), "=r"(r1), "=r"(r2), "=r"(r3) : "r"(addr));
}
__device__ __forceinline__ void mma16816(float* c, const uint32_t* a,
                                         uint32_t b0, uint32_t b1) {
    asm volatile(
        "mma.sync.aligned.m16n8k16.row.col.f32.bf16.bf16.f32 "
        "{%0,%1,%2,%3}, {%4,%5,%6,%7}, {%8,%9}, {%0,%1,%2,%3};"
        : "+f"(c[0]), "+f"(c[1]), "+f"(c[2]), "+f"(c[3])
        : "r"(a[0]), "r"(a[1]), "r"(a[2]), "r"(a[3]), "r"(b0), "r"(b1));
}
__device__ __forceinline__ uint32_t packbf(float lo, float hi) {
    uint32_t r;
    asm("cvt.rn.bf16x2.f32 %0, %1, %2;" : "=r"(r) : "f"(hi), "f"(lo));
    return r;
}
__device__ __forceinline__ void cpasync16(uint32_t dst, const void* src) {
    asm volatile("cp.async.cg.shared.global [%0], [%1], 16;" :: "r"(dst), "l"(src));
}
#define CP_COMMIT()  asm volatile("cp.async.commit_group;" ::: "memory")
#define CP_WAIT(n)   asm volatile("cp.async.wait_group %0;" :: "n"(n) : "memory")

#define LDB 272            // smem bytes per 128-bf16 row (136 halves, conflict-free ldmatrix)
#define TILE (128 * LDB)

// ---------------------------------------------------------------------------
// Kernel 1: GroupNorm statistics only. One block per (b, group). 1024 threads.
// ---------------------------------------------------------------------------
__global__ __launch_bounds__(1024) void gnstat_kernel(const float* __restrict__ x) {
    __shared__ float rs[1024], rs2[1024];
    int tid = threadIdx.x;
    int b = blockIdx.x >> 5;
    int g = blockIdx.x & 31;
    const float4* xp = (const float4*)(x + ((size_t)b * C + g * CPG) * NSP);

    float s = 0.f, s2 = 0.f;
    #pragma unroll 4
    for (int i = tid; i < CPG * NSP / 4; i += 1024) {
        float4 v = xp[i];
        s  += v.x + v.y + v.z + v.w;
        s2 += v.x * v.x + v.y * v.y + v.z * v.z + v.w * v.w;
    }
    rs[tid] = s; rs2[tid] = s2;
    __syncthreads();
    #pragma unroll
    for (int off = 512; off > 0; off >>= 1) {
        if (tid < off) { rs[tid] += rs[tid + off]; rs2[tid] += rs2[tid + off]; }
        __syncthreads();
    }
    if (tid == 0) {
        const float invN = 1.0f / (CPG * NSP);
        float mean = rs[0] * invN;
        float var  = rs2[0] * invN - mean * mean;
        g_stat[blockIdx.x] = make_float2(mean, rsqrtf(var + 1e-5f));
    }
}

// ---------------------------------------------------------------------------
// Kernel 2: QKV projection, HMMA bf16, GN fused, ALL 3 ROLES per CTA.
// grid (32 s-tiles, B). X tile staged once; W restaged per role.
// smem: Xs [c][s] | Ws [o][c]
// ---------------------------------------------------------------------------
__global__ __launch_bounds__(256, 1) void qkv_kernel(const float* __restrict__ x,
                                                     const float* __restrict__ gw,
                                                     const float* __restrict__ gb,
                                                     const float* __restrict__ wq,
                                                     const float* __restrict__ bias) {
    extern __shared__ char smraw[];
    uint32_t smem = smem_u32(smraw);
    const uint32_t Xs = smem;                 // [c][s] bf16, LDB rows
    const uint32_t Ws = smem + TILE;          // [o][c] bf16

    int tid = threadIdx.x;
    int w = tid >> 5, t = tid & 31;
    int s0 = blockIdx.x * 128;
    int b  = blockIdx.y;

    // stage X tile [c][s] with GN applied (once)
    for (int i = tid; i < 128 * 32; i += 256) {
        int c = i >> 5, s4 = i & 31;
        float2 st = g_stat[b * G + (c >> 2)];
        float wch = gw[c] * st.y;
        float bch = gb[c] - st.x * wch;
        float4 v = ((const float4*)(x + ((size_t)b * C + c) * NSP + s0))[s4];
        uint2 pk;
        pk.x = packbf(v.x * wch + bch, v.y * wch + bch);
        pk.y = packbf(v.z * wch + bch, v.w * wch + bch);
        *(uint2*)(smraw + c * LDB + s4 * 8) = pk;
    }
    // stage W role 0
    for (int i = tid; i < 128 * 32; i += 256) {
        int o = i >> 5, c4 = i & 31;
        float4 v = ((const float4*)(wq + (size_t)o * 128))[c4];
        uint2 pk;
        pk.x = packbf(v.x, v.y);
        pk.y = packbf(v.z, v.w);
        *(uint2*)(smraw + TILE + o * LDB + c4 * 8) = pk;
    }
    __syncthreads();

    // A fragments from Xs^T (shared by roles 0,1):
    // row(k=c) = (t&7) + ((t>>4)&1)*8 (+j*16); col(m=s) = w*16 + ((t>>3)&1)*8
    uint32_t afx[8][4];
    {
        uint32_t abase = Xs + (uint32_t)(((t & 7) + ((t >> 4) & 1) * 8) * LDB
                                         + (w * 16 + ((t >> 3) & 1) * 8) * 2);
        #pragma unroll
        for (int j = 0; j < 8; j++)
            ldsm4t(afx[j][0], afx[j][1], afx[j][2], afx[j][3], abase + j * (16 * LDB));
    }

    const uint32_t bqk = Ws + (uint32_t)(((t & 7) + ((t >> 4) << 3)) * LDB
                                         + ((t >> 3) & 1) * 16);
    const float scale = 0.1275174331f;   // 128^-0.5 * log2(e)

    // ---- roles 0 (q) and 1 (k) ----
    #pragma unroll
    for (int role = 0; role < 2; role++) {
        if (role == 1) {
            __syncthreads();   // prior role's ldmatrix done
            for (int i = tid; i < 128 * 32; i += 256) {
                int o = i >> 5, c4 = i & 31;
                float4 v = ((const float4*)(wq + (size_t)(128 + o) * 128))[c4];
                uint2 pk;
                pk.x = packbf(v.x, v.y);
                pk.y = packbf(v.z, v.w);
                *(uint2*)(smraw + TILE + o * LDB + c4 * 8) = pk;
            }
            __syncthreads();
        }

        float acc[16][4];
        #pragma unroll
        for (int n = 0; n < 16; n++) { acc[n][0] = acc[n][1] = acc[n][2] = acc[n][3] = 0.f; }

        #pragma unroll
        for (int n2 = 0; n2 < 8; n2++) {
            uint32_t baddr = bqk + n2 * (16 * LDB);
            #pragma unroll
            for (int j = 0; j < 8; j++) {
                uint32_t f0, f1, f2, f3;
                ldsm4(f0, f1, f2, f3, baddr + j * 32);
                mma16816(acc[2 * n2],     afx[j], f0, f1);
                mma16816(acc[2 * n2 + 1], afx[j], f2, f3);
            }
        }

        // epilogue: rows s = s0 + w*16 + (t>>2) (+8), cols o = n*8 + 2*(t&3)
        int r0 = s0 + w * 16 + (t >> 2), r1 = r0 + 8;
        __nv_bfloat16* dst = (role == 0) ? g_qh : g_kh;
        #pragma unroll
        for (int n = 0; n < 16; n++) {
            int col = n * 8 + 2 * (t & 3);
            float bv0 = bias[role * 128 + col];
            float bv1 = bias[role * 128 + col + 1];
            float v00 = acc[n][0] + bv0, v01 = acc[n][1] + bv1;
            float v10 = acc[n][2] + bv0, v11 = acc[n][3] + bv1;
            if (role == 0) { v00 *= scale; v01 *= scale; v10 *= scale; v11 *= scale; }
            *(uint32_t*)(dst + ((size_t)(b * NSP + r0) << 7) + col) = packbf(v00, v01);
            *(uint32_t*)(dst + ((size_t)(b * NSP + r1) << 7) + col) = packbf(v10, v11);
        }
    }

    // ---- role 2 (v): A = W (m=o), B = Xs^T (n=s) ----
    __syncthreads();
    for (int i = tid; i < 128 * 32; i += 256) {
        int o = i >> 5, c4 = i & 31;
        float4 v = ((const float4*)(wq + (size_t)(256 + o) * 128))[c4];
        uint2 pk;
        pk.x = packbf(v.x, v.y);
        pk.y = packbf(v.z, v.w);
        *(uint2*)(smraw + TILE + o * LDB + c4 * 8) = pk;
    }
    __syncthreads();

    {
        uint32_t afw[8][4];
        uint32_t abase = Ws + (uint32_t)((w * 16 + (t & 7) + ((t >> 3) & 1) * 8) * LDB
                                         + (t >> 4) * 16);
        #pragma unroll
        for (int j = 0; j < 8; j++)
            ldsm4(afw[j][0], afw[j][1], afw[j][2], afw[j][3], abase + j * 32);

        float acc[16][4];
        #pragma unroll
        for (int n = 0; n < 16; n++) { acc[n][0] = acc[n][1] = acc[n][2] = acc[n][3] = 0.f; }

        uint32_t bbase = Xs + (uint32_t)(((t & 7) + ((t >> 3) & 1) * 8) * LDB
                                         + (((t >> 4) & 1) * 8) * 2);
        #pragma unroll
        for (int n2 = 0; n2 < 8; n2++) {
            uint32_t baddr = bbase + n2 * 32;          // 16 cols * 2B
            #pragma unroll
            for (int j = 0; j < 8; j++) {
                uint32_t f0, f1, f2, f3;
                ldsm4t(f0, f1, f2, f3, baddr + j * (16 * LDB));
                mma16816(acc[2 * n2],     afw[j], f0, f1);
                mma16816(acc[2 * n2 + 1], afw[j], f2, f3);
            }
        }

        int o0 = w * 16 + (t >> 2), o1 = o0 + 8;
        float bv0 = bias[256 + o0], bv1 = bias[256 + o1];
        #pragma unroll
        for (int n = 0; n < 16; n++) {
            int col = n * 8 + 2 * (t & 3);
            *(uint32_t*)(g_vt + ((size_t)(b * C + o0) << 12) + s0 + col) =
                packbf(acc[n][0] + bv0, acc[n][1] + bv0);
            *(uint32_t*)(g_vt + ((size_t)(b * C + o1) << 12) + s0 + col) =
                packbf(acc[n][2] + bv1, acc[n][3] + bv1);
        }
    }
}

// ---------------------------------------------------------------------------
// Kernel 3: flash attention, HMMA bf16, 2-stage cp.async K/V pipeline.
// smem: Q | K0 | V0 | K1 | V1  (5 tiles)
// ---------------------------------------------------------------------------
#define SM_ATTN (5 * TILE)

__global__ __launch_bounds__(256, 1) void attn_kernel() {
    extern __shared__ char smraw[];
    uint32_t smem = smem_u32(smraw);
    const uint32_t Qs = smem;

    int tid = threadIdx.x;
    int w = tid >> 5, t = tid & 31;
    int b = blockIdx.y, q0 = blockIdx.x * 128;

    int sr = tid >> 4, sc = tid & 15;

    {
        const char* qsrc = (const char*)(g_qh + ((size_t)(b * NSP + q0) << 7));
        #pragma unroll
        for (int rr = 0; rr < 8; rr++) {
            int r = sr + rr * 16;
            cpasync16(Qs + r * LDB + sc * 16, qsrc + r * 256 + sc * 16);
        }
    }
    CP_COMMIT();

    const char* kbase = (const char*)(g_kh + ((size_t)b * NSP << 7));
    const char* vbase = (const char*)(g_vt + ((size_t)b * C << 12));
    #pragma unroll
    for (int rr = 0; rr < 8; rr++) {
        int r = sr + rr * 16;
        cpasync16(smem + TILE + r * LDB + sc * 16, kbase + r * 256 + sc * 16);
        cpasync16(smem + 2 * TILE + r * LDB + sc * 16, vbase + (size_t)r * 8192 + sc * 16);
    }
    CP_COMMIT();

    CP_WAIT(1);
    __syncthreads();
    uint32_t qf[8][4];
    {
        uint32_t qbase = Qs + (uint32_t)((w * 16 + (t & 7) + ((t >> 3) & 1) * 8) * LDB
                                         + (t >> 4) * 16);
        #pragma unroll
        for (int j = 0; j < 8; j++)
            ldsm4(qf[j][0], qf[j][1], qf[j][2], qf[j][3], qbase + j * 32);
    }

    uint32_t kvoff = (uint32_t)(((t & 7) + ((t >> 4) << 3)) * LDB + ((t >> 3) & 1) * 16);

    float O[16][4];
    #pragma unroll
    for (int n = 0; n < 16; n++) { O[n][0] = O[n][1] = O[n][2] = O[n][3] = 0.f; }
    float m0 = -1e30f, m1 = -1e30f, l0r = 0.f, l1r = 0.f;

    for (int kt = 0; kt < NSP / 128; kt++) {
        int cur = kt & 1;
        if (kt + 1 < NSP / 128) {
            __syncthreads();
            int nb = cur ^ 1;
            #pragma unroll
            for (int rr = 0; rr < 8; rr++) {
                int r = sr + rr * 16;
                cpasync16(smem + (1 + 2 * nb) * TILE + r * LDB + sc * 16,
                          kbase + (size_t)(kt + 1) * 32768 + r * 256 + sc * 16);
                cpasync16(smem + (2 + 2 * nb) * TILE + r * LDB + sc * 16,
                          vbase + (size_t)r * 8192 + (size_t)(kt + 1) * 256 + sc * 16);
            }
            CP_COMMIT();
            CP_WAIT(1);
        } else {
            CP_WAIT(0);
        }
        __syncthreads();

        uint32_t kb = smem + (1 + 2 * cur) * TILE + kvoff;
        uint32_t vb = smem + (2 + 2 * cur) * TILE + kvoff;

        float S[16][4];
        #pragma unroll
        for (int n = 0; n < 16; n++) { S[n][0] = S[n][1] = S[n][2] = S[n][3] = 0.f; }
        #pragma unroll
        for (int n2 = 0; n2 < 8; n2++) {
            uint32_t kaddr = kb + n2 * (16 * LDB);
            #pragma unroll
            for (int j = 0; j < 8; j++) {
                uint32_t f0, f1, f2, f3;
                ldsm4(f0, f1, f2, f3, kaddr + j * 32);
                mma16816(S[2 * n2],     qf[j], f0, f1);
                mma16816(S[2 * n2 + 1], qf[j], f2, f3);
            }
        }

        float mx0 = -1e30f, mx1 = -1e30f;
        #pragma unroll
        for (int n = 0; n < 16; n++) {
            mx0 = fmaxf(mx0, fmaxf(S[n][0], S[n][1]));
            mx1 = fmaxf(mx1, fmaxf(S[n][2], S[n][3]));
        }
        mx0 = fmaxf(mx0, __shfl_xor_sync(0xffffffffu, mx0, 1));
        mx0 = fmaxf(mx0, __shfl_xor_sync(0xffffffffu, mx0, 2));
        mx1 = fmaxf(mx1, __shfl_xor_sync(0xffffffffu, mx1, 1));
        mx1 = fmaxf(mx1, __shfl_xor_sync(0xffffffffu, mx1, 2));
        float mn0 = fmaxf(m0, mx0), mn1 = fmaxf(m1, mx1);
        float a0 = exp2f(m0 - mn0), a1 = exp2f(m1 - mn1);
        m0 = mn0; m1 = mn1;

        float s0 = 0.f, s1 = 0.f;
        #pragma unroll
        for (int n = 0; n < 16; n++) {
            S[n][0] = exp2f(S[n][0] - mn0);
            S[n][1] = exp2f(S[n][1] - mn0);
            S[n][2] = exp2f(S[n][2] - mn1);
            S[n][3] = exp2f(S[n][3] - mn1);
            s0 += S[n][0] + S[n][1];
            s1 += S[n][2] + S[n][3];
        }
        s0 += __shfl_xor_sync(0xffffffffu, s0, 1);
        s0 += __shfl_xor_sync(0xffffffffu, s0, 2);
        s1 += __shfl_xor_sync(0xffffffffu, s1, 1);
        s1 += __shfl_xor_sync(0xffffffffu, s1, 2);
        l0r = l0r * a0 + s0;
        l1r = l1r * a1 + s1;

        #pragma unroll
        for (int n = 0; n < 16; n++) {
            O[n][0] *= a0; O[n][1] *= a0; O[n][2] *= a1; O[n][3] *= a1;
        }

        #pragma unroll
        for (int j = 0; j < 8; j++) {
            uint32_t pa[4];
            pa[0] = packbf(S[2 * j][0],     S[2 * j][1]);
            pa[1] = packbf(S[2 * j][2],     S[2 * j][3]);
            pa[2] = packbf(S[2 * j + 1][0], S[2 * j + 1][1]);
            pa[3] = packbf(S[2 * j + 1][2], S[2 * j + 1][3]);
            uint32_t vaddr = vb + j * 32;
            #pragma unroll
            for (int d2 = 0; d2 < 8; d2++) {
                uint32_t f0, f1, f2, f3;
                ldsm4(f0, f1, f2, f3, vaddr + d2 * (16 * LDB));
                mma16816(O[2 * d2],     pa, f0, f1);
                mma16816(O[2 * d2 + 1], pa, f2, f3);
            }
        }
    }

    float r0 = 1.0f / l0r, r1 = 1.0f / l1r;
    int g = t >> 2, tg = t & 3;
    __nv_bfloat16* dst0 = g_aoh + ((size_t)(b * NSP + q0 + w * 16 + g) << 7) + tg * 2;
    __nv_bfloat16* dst1 = dst0 + (8 << 7);
    #pragma unroll
    for (int n = 0; n < 16; n++) {
        *(uint32_t*)(dst0 + n * 8) = packbf(O[n][0] * r0, O[n][1] * r0);
        *(uint32_t*)(dst1 + n * 8) = packbf(O[n][2] * r1, O[n][3] * r1);
    }
}

// ---------------------------------------------------------------------------
// Kernel 4: out projection HMMA + bias + residual.
// ---------------------------------------------------------------------------
__global__ __launch_bounds__(256, 1) void oproj_kernel(const float* __restrict__ wo,
                                                       const float* __restrict__ bias,
                                                       const float* __restrict__ x,
                                                       float* __restrict__ out) {
    extern __shared__ char smraw[];
    uint32_t smem = smem_u32(smraw);
    const uint32_t As = smem;
    const uint32_t Ws = smem + TILE;

    int tid = threadIdx.x;
    int w = tid >> 5, t = tid & 31;
    int s0 = blockIdx.x * 128;
    int b  = blockIdx.y;

    for (int i = tid; i < 128 * 16; i += 256) {
        int r = i >> 4, c8 = i & 15;
        uint4 v = ((const uint4*)(g_aoh + ((size_t)(b * NSP + s0 + r) << 7)))[c8];
        *(uint4*)(smraw + r * LDB + c8 * 16) = v;
    }
    for (int i = tid; i < 128 * 32; i += 256) {
        int o = i >> 5, c4 = i & 31;
        float4 v = ((const float4*)(wo + (size_t)o * 128))[c4];
        uint2 pk;
        pk.x = packbf(v.x, v.y);
        pk.y = packbf(v.z, v.w);
        *(uint2*)(smraw + TILE + o * LDB + c4 * 8) = pk;
    }
    __syncthreads();

    uint32_t af[8][4];
    uint32_t abase = Ws + (uint32_t)((w * 16 + (t & 7) + ((t >> 3) & 1) * 8) * LDB
                                     + (t >> 4) * 16);
    #pragma unroll
    for (int j = 0; j < 8; j++)
        ldsm4(af[j][0], af[j][1], af[j][2], af[j][3], abase + j * 32);

    float acc[16][4];
    #pragma unroll
    for (int n = 0; n < 16; n++) { acc[n][0] = acc[n][1] = acc[n][2] = acc[n][3] = 0.f; }

    uint32_t bbase = As + (uint32_t)(((t & 7) + ((t >> 4) << 3)) * LDB
                                     + ((t >> 3) & 1) * 16);
    #pragma unroll
    for (int n2 = 0; n2 < 8; n2++) {
        uint32_t baddr = bbase + n2 * (16 * LDB);
        #pragma unroll
        for (int j = 0; j < 8; j++) {
            uint32_t f0, f1, f2, f3;
            ldsm4(f0, f1, f2, f3, baddr + j * 32);
            mma16816(acc[2 * n2],     af[j], f0, f1);
            mma16816(acc[2 * n2 + 1], af[j], f2, f3);
        }
    }

    int o0 = w * 16 + (t >> 2), o1 = o0 + 8;
    float bv0 = bias[o0], bv1 = bias[o1];
    #pragma unroll
    for (int n = 0; n < 16; n++) {
        int col = n * 8 + 2 * (t & 3);
        size_t base0 = ((size_t)(b * C + o0) << 12) + s0 + col;
        size_t base1 = ((size_t)(b * C + o1) << 12) + s0 + col;
        float2 xv0 = *(const float2*)(x + base0);
        float2 xv1 = *(const float2*)(x + base1);
        *(float2*)(out + base0) = make_float2(acc[n][0] + bv0 + xv0.x,
                                              acc[n][1] + bv0 + xv0.y);
        *(float2*)(out + base1) = make_float2(acc[n][2] + bv1 + xv1.x,
                                              acc[n][3] + bv1 + xv1.y);
    }
}

// ---------------------------------------------------------------------------
extern "C" void kernel_launch(void* const* d_in, const int* in_sizes, int n_in,
                              void* d_out, int out_size) {
    const float* x     = (const float*)d_in[0];
    const float* gn_w  = (const float*)d_in[1];
    const float* gn_b  = (const float*)d_in[2];
    const float* qkv_w = (const float*)d_in[3];
    const float* qkv_b = (const float*)d_in[4];
    const float* out_w = (const float*)d_in[5];
    const float* out_b = (const float*)d_in[6];
    float* out = (float*)d_out;

    static bool attrs_set = false;
    const int tile2_smem = 2 * TILE;
    if (!attrs_set) {
        cudaFuncSetAttribute(qkv_kernel,   cudaFuncAttributeMaxDynamicSharedMemorySize, tile2_smem);
        cudaFuncSetAttribute(oproj_kernel, cudaFuncAttributeMaxDynamicSharedMemorySize, tile2_smem);
        cudaFuncSetAttribute(attn_kernel,  cudaFuncAttributeMaxDynamicSharedMemorySize, SM_ATTN);
        attrs_set = true;
    }

    gnstat_kernel<<<B * G, 1024>>>(x);
    qkv_kernel<<<dim3(NSP / 128, B), 256, tile2_smem>>>(x, gn_w, gn_b, qkv_w, qkv_b);
    attn_kernel<<<dim3(NSP / 128, B), 256, SM_ATTN>>>();
    oproj_kernel<<<dim3(NSP / 128, B), 256, tile2_smem>>>(out_w, out_b, x, out);
}